// round 4
// baseline (speedup 1.0000x reference)
#include <cuda_runtime.h>
#include <math.h>

#define B_    16
#define C_    64
#define H_    160
#define W_    160
#define OUT_  64
#define KEXP  4
#define HID   17
#define TEMPR 34.0f
#define HW    (H_*W_)

#define TILE  32
#define CHK   4          // channels per smem chunk (x stored duplicated -> 8B/px)
#define OCG   16         // output channels per block (8 f32x2 pairs per thread)

typedef unsigned long long ull;

// Scratch (device globals: no allocation allowed in kernel_launch)
__device__ float g_pooled[B_*C_];
__device__ float g_attn[B_*KEXP];
__device__ float g_aggb[B_*OUT_];
__device__ float g_aggw[B_*OUT_*C_*9];

// ---------- Blackwell packed f32x2 helpers ----------
__device__ __forceinline__ void ffma2(ull& d, ull a, ull b) {
    asm("fma.rn.f32x2 %0, %1, %2, %0;" : "+l"(d) : "l"(a), "l"(b));
}
__device__ __forceinline__ ull dup2(float v) {
    ull r;
    asm("mov.b64 %0, {%1, %1};" : "=l"(r) : "f"(v));
    return r;
}
__device__ __forceinline__ void unpack2(ull v, float& lo, float& hi) {
    asm("mov.b64 {%0, %1}, %2;" : "=f"(lo), "=f"(hi) : "l"(v));
}

// ---------- 1. global average pool ----------
__global__ void pool_kernel(const float* __restrict__ x) {
    int bc = blockIdx.x;                       // 0..1023
    const float4* p = (const float4*)(x + (size_t)bc * HW);
    float s = 0.f;
    for (int i = threadIdx.x; i < HW/4; i += blockDim.x) {
        float4 v = p[i];
        s += (v.x + v.y) + (v.z + v.w);
    }
    #pragma unroll
    for (int o = 16; o; o >>= 1) s += __shfl_xor_sync(0xffffffffu, s, o);
    __shared__ float red[8];
    if ((threadIdx.x & 31) == 0) red[threadIdx.x >> 5] = s;
    __syncthreads();
    if (threadIdx.x == 0) {
        float t = 0.f;
        #pragma unroll
        for (int i = 0; i < 8; i++) t += red[i];
        g_pooled[bc] = t * (1.0f / (float)HW);
    }
}

// ---------- 2. attention MLP + softmax + agg bias ----------
__global__ void attn_kernel(const float* __restrict__ fc1,
                            const float* __restrict__ fc2,
                            const float* __restrict__ bias_p) {
    int b = threadIdx.x;
    if (b >= B_) return;
    float pooled[C_];
    #pragma unroll
    for (int c = 0; c < C_; c++) pooled[c] = g_pooled[b*C_ + c];
    float hid[HID];
    for (int j = 0; j < HID; j++) {
        float s = 0.f;
        #pragma unroll
        for (int c = 0; c < C_; c++) s += pooled[c] * fc1[j*C_ + c];
        hid[j] = fmaxf(s, 0.f);
    }
    float lg[KEXP];
    for (int k = 0; k < KEXP; k++) {
        float s = 0.f;
        #pragma unroll
        for (int j = 0; j < HID; j++) s += hid[j] * fc2[k*HID + j];
        lg[k] = s * (1.0f / TEMPR);
    }
    float m = fmaxf(fmaxf(lg[0], lg[1]), fmaxf(lg[2], lg[3]));
    float e[KEXP], sum = 0.f;
    for (int k = 0; k < KEXP; k++) { e[k] = expf(lg[k] - m); sum += e[k]; }
    float a[KEXP];
    for (int k = 0; k < KEXP; k++) { a[k] = e[k] / sum; g_attn[b*KEXP + k] = a[k]; }
    for (int o = 0; o < OUT_; o++) {
        float s = 0.f;
        #pragma unroll
        for (int k = 0; k < KEXP; k++) s += a[k] * bias_p[k*OUT_ + o];
        g_aggb[b*OUT_ + o] = s;
    }
}

// ---------- 3. aggregate weights ----------
__global__ void aggw_kernel(const float* __restrict__ weight) {
    int idx = blockIdx.x * blockDim.x + threadIdx.x;
    const int R = OUT_*C_*9;                    // 36864
    if (idx >= B_*R) return;
    int b = idx / R;
    int r = idx - b*R;
    float s = 0.f;
    #pragma unroll
    for (int k = 0; k < KEXP; k++)
        s += g_attn[b*KEXP + k] * weight[(size_t)k*R + r];
    g_aggw[idx] = s;
}

// ---------- 4. per-batch 3x3 conv, FFMA2-dense mainloop ----------
// Block: 32x32 output tile, 16 ocs. Thread: 2x2 pixels x 8 oc-pairs.
// x staged in smem PRE-DUPLICATED ({v,v} per pixel) so the broadcast operand
// is a single LDS.64 — zero ALU MOVs in the mainloop.
__global__ __launch_bounds__(256)
void conv_kernel(const float* __restrict__ x, float* __restrict__ out) {
    __shared__ ull xsd[CHK][34][36];           // duplicated pixels, padded stride
    __shared__ float ws[CHK][9][OCG];          // oc contiguous -> natural f32x2 pairs

    int bz  = blockIdx.z;
    int b   = bz >> 2;                         // 4 oc-groups of 16
    int og  = bz & 3;
    int ty0 = blockIdx.y * TILE;
    int tx0 = blockIdx.x * TILE;
    int tid = threadIdx.x;
    int tx  = tid & 15;                        // 16 x-positions (2 px each)
    int ty  = tid >> 4;                        // 16 y-positions (2 px each)

    // acc[pixel 0..3 (row*2+col)][oc-pair 0..7]
    ull acc[4][8];
    #pragma unroll
    for (int i = 0; i < 4; i++)
        #pragma unroll
        for (int j = 0; j < 8; j++) acc[i][j] = 0ull;

    const float* xb = x + (size_t)b * C_ * HW;

    for (int cc = 0; cc < C_; cc += CHK) {
        // stage x chunk, duplicated, halo + zero-pad
        for (int i = tid; i < CHK*34*34; i += 256) {
            int c  = i / (34*34);
            int r  = i - c*(34*34);
            int yy = r / 34;
            int xx = r - yy*34;
            int gy = ty0 + yy - 1;
            int gx = tx0 + xx - 1;
            float v = 0.f;
            if (gy >= 0 && gy < H_ && gx >= 0 && gx < W_)
                v = __ldg(xb + (size_t)(cc + c)*HW + gy*W_ + gx);
            xsd[c][yy][xx] = dup2(v);
        }
        // stage weight chunk (16 ocs x 9 taps x CHK channels)
        for (int i = tid; i < CHK*9*OCG; i += 256) {
            int c  = i / (9*OCG);
            int r  = i - c*(9*OCG);
            int ij = r / OCG;
            int oc = r - ij*OCG;
            ws[c][ij][oc] =
                g_aggw[(((b*OUT_) + og*OCG + oc)*C_ + cc + c)*9 + ij];
        }
        __syncthreads();

        #pragma unroll
        for (int c = 0; c < CHK; ++c) {
            #pragma unroll
            for (int ki = 0; ki < 3; ++ki) {
                #pragma unroll
                for (int kj = 0; kj < 3; ++kj) {
                    const ull* xr = &xsd[c][ty*2 + ki][tx*2 + kj];
                    ull xd0 = xr[0];
                    ull xd1 = xr[1];
                    ull xd2 = xr[36];
                    ull xd3 = xr[37];
                    const ull* wq = (const ull*)&ws[c][ki*3 + kj][0];
                    #pragma unroll
                    for (int p = 0; p < 8; ++p) {
                        ull w = wq[p];
                        ffma2(acc[0][p], xd0, w);
                        ffma2(acc[1][p], xd1, w);
                        ffma2(acc[2][p], xd2, w);
                        ffma2(acc[3][p], xd3, w);
                    }
                }
            }
        }
        __syncthreads();
    }

    // epilogue: unpack, add bias, coalesced float2 stores
    int py = ty0 + ty*2;
    int px = tx0 + tx*2;
    #pragma unroll
    for (int pr = 0; pr < 8; ++pr) {
        float2 bias2 = *(const float2*)&g_aggb[b*OUT_ + og*OCG + pr*2];
        #pragma unroll
        for (int row = 0; row < 2; ++row) {
            float lo0, hi0, lo1, hi1;
            unpack2(acc[row*2 + 0][pr], lo0, hi0);   // pixel (row, 0)
            unpack2(acc[row*2 + 1][pr], lo1, hi1);   // pixel (row, 1)
            float* o0 = out + (((size_t)b*OUT_ + og*OCG + pr*2)*H_ + (py + row))*W_ + px;
            float* o1 = o0 + (size_t)HW;
            *(float2*)o0 = make_float2(lo0 + bias2.x, lo1 + bias2.x);
            *(float2*)o1 = make_float2(hi0 + bias2.y, hi1 + bias2.y);
        }
    }
}

extern "C" void kernel_launch(void* const* d_in, const int* in_sizes, int n_in,
                              void* d_out, int out_size) {
    const float* x      = (const float*)d_in[0];
    const float* fc1    = (const float*)d_in[1];
    const float* fc2    = (const float*)d_in[2];
    const float* weight = (const float*)d_in[3];
    const float* bias_p = (const float*)d_in[4];
    float* out = (float*)d_out;

    pool_kernel<<<B_*C_, 256>>>(x);
    attn_kernel<<<1, 32>>>(fc1, fc2, bias_p);
    aggw_kernel<<<(B_*OUT_*C_*9 + 255)/256, 256>>>(weight);
    dim3 grid(W_/TILE, H_/TILE, B_*(OUT_/OCG));
    conv_kernel<<<grid, 256>>>(x, out);
}

// round 6
// speedup vs baseline: 2.3528x; 2.3528x over previous
#include <cuda_runtime.h>
#include <cuda_bf16.h>
#include <stdint.h>
#include <math.h>

#define B_    16
#define C_    64
#define H_    160
#define W_    160
#define OUT_  64
#define KEXP  4
#define HID   17
#define TEMPR 34.0f
#define HW    25600

// ---- flat padded image: [b][px][64ch] bf16, 128B per pixel ----
#define PWROW   168
#define XIMG    27216                    // 162*168
#define XGUARD  256
#define XPXTOT  27728                    // 256 + 27216 + 256
#define XREGB   3549184ULL               // 27728*128
// ---- tiling ----
#define MTILE   128
#define NT_PER_B 210                     // (160*168)/128
#define STRIP   466                      // 128 + 2*169
#define SROW_B  144                      // padded smem row stride (bytes)
// ---- smem layout ----
#define OFF_XH  0
#define XH_SZ   (STRIP*SROW_B)           // 67104
#define OFF_XL  67104
#define OFF_W   134208                   // 2 bufs x 128 rows x 144
#define WBUF_SZ 18432
#define DYN_SMEM 171072

__device__ __align__(128) unsigned char g_xhi[16*XREGB];
__device__ __align__(128) unsigned char g_xlo[16*XREGB];
__device__ __align__(128) unsigned char g_wp[16*9*16384];
__device__ float g_pooled[B_*C_];
__device__ float g_attn[B_*KEXP];
__device__ float g_aggb[B_*OUT_];

__device__ __forceinline__ uint32_t smem_u32(const void* p) {
    uint32_t a;
    asm("{ .reg .u64 t; cvta.to.shared.u64 t, %1; cvt.u32.u64 %0, t; }" : "=r"(a) : "l"(p));
    return a;
}
__device__ __forceinline__ void cp16(uint32_t dst, const void* src) {
    asm volatile("cp.async.cg.shared.global [%0], [%1], 16;" :: "r"(dst), "l"(src) : "memory");
}
#define CP_COMMIT() asm volatile("cp.async.commit_group;" ::: "memory")
#define CP_WAIT0()  asm volatile("cp.async.wait_group 0;" ::: "memory")

#define LDM4(r, a) \
    asm volatile("ldmatrix.sync.aligned.m8n8.x4.shared.b16 {%0,%1,%2,%3}, [%4];" \
        : "=r"((r)[0]), "=r"((r)[1]), "=r"((r)[2]), "=r"((r)[3]) : "r"(a))
#define LDM2(r, a) \
    asm volatile("ldmatrix.sync.aligned.m8n8.x2.shared.b16 {%0,%1}, [%2];" \
        : "=r"((r)[0]), "=r"((r)[1]) : "r"(a))
#define MMA16816(d, a, b) \
    asm volatile("mma.sync.aligned.m16n8k16.row.col.f32.bf16.bf16.f32 " \
        "{%0,%1,%2,%3}, {%4,%5,%6,%7}, {%8,%9}, {%0,%1,%2,%3};" \
        : "+f"((d)[0]), "+f"((d)[1]), "+f"((d)[2]), "+f"((d)[3]) \
        : "r"((a)[0]), "r"((a)[1]), "r"((a)[2]), "r"((a)[3]), "r"((b)[0]), "r"((b)[1]))

// ================= preprocessing =================
__global__ void zero_kernel() {
    const size_t n16 = (16*XREGB)/16;          // per array
    uint4 z = make_uint4(0,0,0,0);
    for (size_t i = (size_t)blockIdx.x*blockDim.x + threadIdx.x; i < n16;
         i += (size_t)gridDim.x*blockDim.x) {
        ((uint4*)g_xhi)[i] = z;
        ((uint4*)g_xlo)[i] = z;
    }
}

__global__ void pool_kernel(const float* __restrict__ x) {
    int bc = blockIdx.x;
    const float4* p = (const float4*)(x + (size_t)bc * HW);
    float s = 0.f;
    for (int i = threadIdx.x; i < HW/4; i += blockDim.x) {
        float4 v = p[i];
        s += (v.x + v.y) + (v.z + v.w);
    }
    #pragma unroll
    for (int o = 16; o; o >>= 1) s += __shfl_xor_sync(0xffffffffu, s, o);
    __shared__ float red[8];
    if ((threadIdx.x & 31) == 0) red[threadIdx.x >> 5] = s;
    __syncthreads();
    if (threadIdx.x == 0) {
        float t = 0.f;
        #pragma unroll
        for (int i = 0; i < 8; i++) t += red[i];
        g_pooled[bc] = t * (1.0f / (float)HW);
    }
}

__global__ void attn_kernel(const float* __restrict__ fc1,
                            const float* __restrict__ fc2,
                            const float* __restrict__ bias_p) {
    int b = threadIdx.x;
    if (b >= B_) return;
    float pooled[C_];
    #pragma unroll
    for (int c = 0; c < C_; c++) pooled[c] = g_pooled[b*C_ + c];
    float hid[HID];
    for (int j = 0; j < HID; j++) {
        float s = 0.f;
        #pragma unroll
        for (int c = 0; c < C_; c++) s += pooled[c] * fc1[j*C_ + c];
        hid[j] = fmaxf(s, 0.f);
    }
    float lg[KEXP];
    for (int k = 0; k < KEXP; k++) {
        float s = 0.f;
        #pragma unroll
        for (int j = 0; j < HID; j++) s += hid[j] * fc2[k*HID + j];
        lg[k] = s * (1.0f / TEMPR);
    }
    float m = fmaxf(fmaxf(lg[0], lg[1]), fmaxf(lg[2], lg[3]));
    float e[KEXP], sum = 0.f;
    for (int k = 0; k < KEXP; k++) { e[k] = expf(lg[k] - m); sum += e[k]; }
    float a[KEXP];
    for (int k = 0; k < KEXP; k++) { a[k] = e[k]/sum; g_attn[b*KEXP + k] = a[k]; }
    for (int o = 0; o < OUT_; o++) {
        float s = 0.f;
        #pragma unroll
        for (int k = 0; k < KEXP; k++) s += a[k] * bias_p[k*OUT_ + o];
        g_aggb[b*OUT_ + o] = s;
    }
}

// transpose + split x -> g_xhi/g_xlo
__global__ __launch_bounds__(256)
void xprep_kernel(const float* __restrict__ x) {
    __shared__ float s[64*33];
    int h  = blockIdx.x;
    int w0 = blockIdx.y * 32;
    int b  = blockIdx.z;
    int t  = threadIdx.x;
    int wd = t >> 5, lane = t & 31;
    #pragma unroll
    for (int i = 0; i < 8; i++) {
        int c = i*8 + wd;
        s[c*33 + lane] = x[(((size_t)b*C_ + c)*H_ + h)*W_ + w0 + lane];
    }
    __syncthreads();
    int px = t >> 3, g = t & 7;
    unsigned short hs[8], ls[8];
    #pragma unroll
    for (int j = 0; j < 8; j++) {
        float v = s[(8*g + j)*33 + px];
        __nv_bfloat16 hb = __float2bfloat16_rn(v);
        float r = v - __bfloat162float(hb);
        hs[j] = __bfloat16_as_ushort(hb);
        ls[j] = __bfloat16_as_ushort(__float2bfloat16_rn(r));
    }
    uint4 hv, lv;
    hv.x = hs[0] | ((uint32_t)hs[1] << 16); hv.y = hs[2] | ((uint32_t)hs[3] << 16);
    hv.z = hs[4] | ((uint32_t)hs[5] << 16); hv.w = hs[6] | ((uint32_t)hs[7] << 16);
    lv.x = ls[0] | ((uint32_t)ls[1] << 16); lv.y = ls[2] | ((uint32_t)ls[3] << 16);
    lv.z = ls[4] | ((uint32_t)ls[5] << 16); lv.w = ls[6] | ((uint32_t)ls[7] << 16);
    uint32_t row = XGUARD + (h + 1)*PWROW + 1 + w0 + px;
    size_t off = (size_t)b*XREGB + (size_t)row*128u + (uint32_t)g*16u;
    *(uint4*)(g_xhi + off) = hv;
    *(uint4*)(g_xlo + off) = lv;
}

// aggregate + split weights: g_wp[b][tap]: rows 0-63 hi(oc), 64-127 lo(oc), 128B rows
__global__ __launch_bounds__(512)
void wprep_kernel(const float* __restrict__ weight) {
    int b = blockIdx.x, tap = blockIdx.y;
    int t = threadIdx.x;
    int oc = t >> 3, g = t & 7;
    float a0 = g_attn[b*KEXP+0], a1 = g_attn[b*KEXP+1],
          a2 = g_attn[b*KEXP+2], a3 = g_attn[b*KEXP+3];
    unsigned short hs[8], ls[8];
    #pragma unroll
    for (int j = 0; j < 8; j++) {
        int c = 8*g + j;
        size_t e = ((size_t)oc*C_ + c)*9 + tap;
        size_t stride = (size_t)OUT_*C_*9;
        float s = a0*weight[e] + a1*weight[e + stride] + a2*weight[e + 2*stride] + a3*weight[e + 3*stride];
        __nv_bfloat16 hb = __float2bfloat16_rn(s);
        float r = s - __bfloat162float(hb);
        hs[j] = __bfloat16_as_ushort(hb);
        ls[j] = __bfloat16_as_ushort(__float2bfloat16_rn(r));
    }
    uint4 hv, lv;
    hv.x = hs[0] | ((uint32_t)hs[1] << 16); hv.y = hs[2] | ((uint32_t)hs[3] << 16);
    hv.z = hs[4] | ((uint32_t)hs[5] << 16); hv.w = hs[6] | ((uint32_t)hs[7] << 16);
    lv.x = ls[0] | ((uint32_t)ls[1] << 16); lv.y = ls[2] | ((uint32_t)ls[3] << 16);
    lv.z = ls[4] | ((uint32_t)ls[5] << 16); lv.w = ls[6] | ((uint32_t)ls[7] << 16);
    size_t tb = ((size_t)b*9 + tap)*16384;
    *(uint4*)(g_wp + tb + (size_t)oc*128u + g*16u) = hv;
    *(uint4*)(g_wp + tb + (size_t)(64 + oc)*128u + g*16u) = lv;
}

// ================= conv: split-bf16 implicit GEMM on mma.sync =================
__global__ __launch_bounds__(256, 1)
void conv_mma_kernel(float* __restrict__ out) {
    extern __shared__ unsigned char smem[];
    uint32_t sb = smem_u32(smem);
    int tid = threadIdx.x, wid = tid >> 5, lane = tid & 31;
    int b = blockIdx.y;
    int n0 = 168 + blockIdx.x * MTILE;

    // ---- stage x strip (hi+lo) and W tap0 ----
    {
        const unsigned char* xs_h = g_xhi + (size_t)b*XREGB + (size_t)(XGUARD + n0 - 169)*128;
        const unsigned char* xs_l = g_xlo + (size_t)b*XREGB + (size_t)(XGUARD + n0 - 169)*128;
        for (int i = tid; i < STRIP*8; i += 256) {
            int r = i >> 3, c = i & 7;
            cp16(sb + OFF_XH + r*SROW_B + c*16, xs_h + (size_t)r*128 + c*16);
            cp16(sb + OFF_XL + r*SROW_B + c*16, xs_l + (size_t)r*128 + c*16);
        }
        const unsigned char* ws = g_wp + ((size_t)b*9 + 0)*16384;
        for (int i = tid; i < 128*8; i += 256) {
            int r = i >> 3, c = i & 7;
            cp16(sb + OFF_W + r*SROW_B + c*16, ws + (size_t)r*128 + c*16);
        }
        CP_COMMIT();
        CP_WAIT0();
        __syncthreads();
    }

    const int wm = (wid & 1) * 64;          // 64 px per warp (4 m16 tiles)
    const int wn = (wid >> 1) * 16;         // 16 oc per warp (2 n8 tiles)
    const int shifts[9] = {-169,-168,-167,-1,0,1,167,168,169};

    float acc[4][2][4];
    #pragma unroll
    for (int i = 0; i < 4; i++)
        #pragma unroll
        for (int j = 0; j < 2; j++)
            #pragma unroll
            for (int k = 0; k < 4; k++) acc[i][j][k] = 0.f;

    const uint32_t a_lane = (uint32_t)(lane & 15)*SROW_B + (uint32_t)(lane >> 4)*16;
    const uint32_t b_lane = (uint32_t)(lane & 7)*SROW_B + (uint32_t)((lane >> 3) & 1)*16;

    for (int tap = 0; tap < 9; tap++) {
        // prefetch next tap's weights into the other buffer
        if (tap < 8) {
            const unsigned char* ws = g_wp + ((size_t)b*9 + tap + 1)*16384;
            uint32_t wdst = sb + OFF_W + ((tap + 1) & 1)*WBUF_SZ;
            for (int i = tid; i < 128*8; i += 256) {
                int r = i >> 3, c = i & 7;
                cp16(wdst + r*SROW_B + c*16, ws + (size_t)r*128 + c*16);
            }
            CP_COMMIT();
        }

        uint32_t wbuf = sb + OFF_W + (tap & 1)*WBUF_SZ;
        uint32_t xrow = sb + OFF_XH + (uint32_t)(169 + shifts[tap] + wm)*SROW_B + a_lane;

        #pragma unroll
        for (int ks = 0; ks < 4; ks++) {
            uint32_t kb = (uint32_t)ks*32;
            uint32_t bh[2][2], bl[2][2];
            #pragma unroll
            for (int ni = 0; ni < 2; ni++) {
                uint32_t ba = wbuf + (uint32_t)(wn + ni*8)*SROW_B + b_lane + kb;
                LDM2(bh[ni], ba);
                LDM2(bl[ni], ba + 64*SROW_B);
            }
            #pragma unroll
            for (int mi = 0; mi < 4; mi++) {
                uint32_t aa = xrow + (uint32_t)mi*(16*SROW_B) + kb;
                uint32_t ah[4], al[4];
                LDM4(ah, aa);
                LDM4(al, aa + (OFF_XL - OFF_XH));
                #pragma unroll
                for (int ni = 0; ni < 2; ni++) {
                    MMA16816(acc[mi][ni], ah, bh[ni]);
                    MMA16816(acc[mi][ni], ah, bl[ni]);
                    MMA16816(acc[mi][ni], al, bh[ni]);
                }
            }
        }
        if (tap < 8) { CP_WAIT0(); }
        __syncthreads();
    }

    // ---- epilogue: direct stores with padded-border filtering ----
    int g = lane >> 2, tc = lane & 3;
    #pragma unroll
    for (int mi = 0; mi < 4; mi++) {
        #pragma unroll
        for (int ni = 0; ni < 2; ni++) {
            int oc = wn + ni*8 + tc*2;
            float2 bias = *(const float2*)&g_aggb[b*OUT_ + oc];
            int pxA = n0 + wm + mi*16 + g;
            #pragma unroll
            for (int half = 0; half < 2; half++) {
                int px = pxA + half*8;
                int pr = px / PWROW;
                int c  = px - pr*PWROW;
                if (c >= 1 && c <= W_) {
                    size_t o = (((size_t)b*OUT_ + oc)*H_ + (pr - 1))*W_ + (c - 1);
                    out[o]      = acc[mi][ni][half*2 + 0] + bias.x;
                    out[o + HW] = acc[mi][ni][half*2 + 1] + bias.y;
                }
            }
        }
    }
}

extern "C" void kernel_launch(void* const* d_in, const int* in_sizes, int n_in,
                              void* d_out, int out_size) {
    const float* x      = (const float*)d_in[0];
    const float* fc1    = (const float*)d_in[1];
    const float* fc2    = (const float*)d_in[2];
    const float* weight = (const float*)d_in[3];
    const float* bias_p = (const float*)d_in[4];
    float* out = (float*)d_out;

    cudaFuncSetAttribute(conv_mma_kernel, cudaFuncAttributeMaxDynamicSharedMemorySize, DYN_SMEM);

    zero_kernel<<<2048, 256>>>();
    pool_kernel<<<B_*C_, 256>>>(x);
    attn_kernel<<<1, 32>>>(fc1, fc2, bias_p);
    xprep_kernel<<<dim3(H_, 5, B_), 256>>>(x);
    wprep_kernel<<<dim3(B_, 9), 512>>>(weight);
    conv_mma_kernel<<<dim3(NT_PER_B, B_), 256, DYN_SMEM>>>(out);
}

// round 7
// speedup vs baseline: 2.5464x; 1.0823x over previous
#include <cuda_runtime.h>
#include <cuda_bf16.h>
#include <stdint.h>
#include <math.h>

#define B_    16
#define C_    64
#define H_    160
#define W_    160
#define OUT_  64
#define KEXP  4
#define HID   17
#define TEMPR 34.0f
#define HW    25600

// ---- flat padded image: [b][px][64ch] bf16, 128B per pixel ----
#define PWROW   168
#define XGUARD  256
#define XPXTOT  27728                    // 256 + 27216 + 256
#define XREGB   3549184ULL               // 27728*128
// ---- tiling ----
#define MTILE   256
#define NT_PER_B 105                     // (160*168)/256
#define STRIP   594                      // 256 + 2*169
#define SROW_B  144                      // padded smem row stride (bytes)
// ---- smem layout ----
#define OFF_XH  0
#define OFF_XL  85536                    // 594*144
#define OFF_W   171072
#define WBUF_SZ 18432
#define DYN_SMEM 207936

__device__ __align__(128) unsigned char g_xhi[16*XREGB];
__device__ __align__(128) unsigned char g_xlo[16*XREGB];
__device__ __align__(128) unsigned char g_wp[16*9*16384];
__device__ float g_pooled[B_*C_];
__device__ float g_attn[B_*KEXP];
__device__ float g_aggb[B_*OUT_];

__device__ __forceinline__ uint32_t smem_u32(const void* p) {
    uint32_t a;
    asm("{ .reg .u64 t; cvta.to.shared.u64 t, %1; cvt.u32.u64 %0, t; }" : "=r"(a) : "l"(p));
    return a;
}
__device__ __forceinline__ void cp16(uint32_t dst, const void* src) {
    asm volatile("cp.async.cg.shared.global [%0], [%1], 16;" :: "r"(dst), "l"(src) : "memory");
}
#define CP_COMMIT() asm volatile("cp.async.commit_group;" ::: "memory")
#define CP_WAIT0()  asm volatile("cp.async.wait_group 0;" ::: "memory")

#define LDM4(r, a) \
    asm volatile("ldmatrix.sync.aligned.m8n8.x4.shared.b16 {%0,%1,%2,%3}, [%4];" \
        : "=r"((r)[0]), "=r"((r)[1]), "=r"((r)[2]), "=r"((r)[3]) : "r"(a))
#define LDM2(r, a) \
    asm volatile("ldmatrix.sync.aligned.m8n8.x2.shared.b16 {%0,%1}, [%2];" \
        : "=r"((r)[0]), "=r"((r)[1]) : "r"(a))
#define MMA16816(d, a, b) \
    asm volatile("mma.sync.aligned.m16n8k16.row.col.f32.bf16.bf16.f32 " \
        "{%0,%1,%2,%3}, {%4,%5,%6,%7}, {%8,%9}, {%0,%1,%2,%3};" \
        : "+f"((d)[0]), "+f"((d)[1]), "+f"((d)[2]), "+f"((d)[3]) \
        : "r"((a)[0]), "r"((a)[1]), "r"((a)[2]), "r"((a)[3]), "r"((b)[0]), "r"((b)[1]))

// ================= preprocessing =================
// zero ONLY the never-written border/guard pixels (~2128 px per batch per array)
__global__ void border_zero_kernel() {
    int b = blockIdx.x;
    size_t base = (size_t)b * XREGB;
    uint4 z = make_uint4(0,0,0,0);
    // front rows [0, 425), back rows [27297, 27728)  (856 rows total)
    for (int i = threadIdx.x; i < 856*8; i += blockDim.x) {
        int r = i >> 3, c = i & 7;
        int row = (r < 425) ? r : (27297 + r - 425);
        size_t off = base + (size_t)row*128u + (uint32_t)c*16u;
        *(uint4*)(g_xhi + off) = z;
        *(uint4*)(g_xlo + off) = z;
    }
    // per-row gaps: h=0..158, 8 px each, at XGUARD + (h+1)*168 + 161
    for (int i = threadIdx.x; i < 159*8*8; i += blockDim.x) {
        int g  = i >> 6;
        int rr = (i >> 3) & 7;
        int c  = i & 7;
        int row = XGUARD + (g + 1)*PWROW + 161 + rr;
        size_t off = base + (size_t)row*128u + (uint32_t)c*16u;
        *(uint4*)(g_xhi + off) = z;
        *(uint4*)(g_xlo + off) = z;
    }
}

__global__ void pool_kernel(const float* __restrict__ x) {
    int bc = blockIdx.x;
    const float4* p = (const float4*)(x + (size_t)bc * HW);
    float s = 0.f;
    for (int i = threadIdx.x; i < HW/4; i += blockDim.x) {
        float4 v = p[i];
        s += (v.x + v.y) + (v.z + v.w);
    }
    #pragma unroll
    for (int o = 16; o; o >>= 1) s += __shfl_xor_sync(0xffffffffu, s, o);
    __shared__ float red[8];
    if ((threadIdx.x & 31) == 0) red[threadIdx.x >> 5] = s;
    __syncthreads();
    if (threadIdx.x == 0) {
        float t = 0.f;
        #pragma unroll
        for (int i = 0; i < 8; i++) t += red[i];
        g_pooled[bc] = t * (1.0f / (float)HW);
    }
}

__global__ void attn_kernel(const float* __restrict__ fc1,
                            const float* __restrict__ fc2,
                            const float* __restrict__ bias_p) {
    int b = threadIdx.x;
    if (b >= B_) return;
    float pooled[C_];
    #pragma unroll
    for (int c = 0; c < C_; c++) pooled[c] = g_pooled[b*C_ + c];
    float hid[HID];
    for (int j = 0; j < HID; j++) {
        float s = 0.f;
        #pragma unroll
        for (int c = 0; c < C_; c++) s += pooled[c] * fc1[j*C_ + c];
        hid[j] = fmaxf(s, 0.f);
    }
    float lg[KEXP];
    for (int k = 0; k < KEXP; k++) {
        float s = 0.f;
        #pragma unroll
        for (int j = 0; j < HID; j++) s += hid[j] * fc2[k*HID + j];
        lg[k] = s * (1.0f / TEMPR);
    }
    float m = fmaxf(fmaxf(lg[0], lg[1]), fmaxf(lg[2], lg[3]));
    float e[KEXP], sum = 0.f;
    for (int k = 0; k < KEXP; k++) { e[k] = expf(lg[k] - m); sum += e[k]; }
    float a[KEXP];
    for (int k = 0; k < KEXP; k++) { a[k] = e[k]/sum; g_attn[b*KEXP + k] = a[k]; }
    for (int o = 0; o < OUT_; o++) {
        float s = 0.f;
        #pragma unroll
        for (int k = 0; k < KEXP; k++) s += a[k] * bias_p[k*OUT_ + o];
        g_aggb[b*OUT_ + o] = s;
    }
}

// transpose + split x -> g_xhi/g_xlo
__global__ __launch_bounds__(256)
void xprep_kernel(const float* __restrict__ x) {
    __shared__ float s[64*33];
    int h  = blockIdx.x;
    int w0 = blockIdx.y * 32;
    int b  = blockIdx.z;
    int t  = threadIdx.x;
    int wd = t >> 5, lane = t & 31;
    #pragma unroll
    for (int i = 0; i < 8; i++) {
        int c = i*8 + wd;
        s[c*33 + lane] = x[(((size_t)b*C_ + c)*H_ + h)*W_ + w0 + lane];
    }
    __syncthreads();
    int px = t >> 3, g = t & 7;
    unsigned short hs[8], ls[8];
    #pragma unroll
    for (int j = 0; j < 8; j++) {
        float v = s[(8*g + j)*33 + px];
        __nv_bfloat16 hb = __float2bfloat16_rn(v);
        float r = v - __bfloat162float(hb);
        hs[j] = __bfloat16_as_ushort(hb);
        ls[j] = __bfloat16_as_ushort(__float2bfloat16_rn(r));
    }
    uint4 hv, lv;
    hv.x = hs[0] | ((uint32_t)hs[1] << 16); hv.y = hs[2] | ((uint32_t)hs[3] << 16);
    hv.z = hs[4] | ((uint32_t)hs[5] << 16); hv.w = hs[6] | ((uint32_t)hs[7] << 16);
    lv.x = ls[0] | ((uint32_t)ls[1] << 16); lv.y = ls[2] | ((uint32_t)ls[3] << 16);
    lv.z = ls[4] | ((uint32_t)ls[5] << 16); lv.w = ls[6] | ((uint32_t)ls[7] << 16);
    uint32_t row = XGUARD + (h + 1)*PWROW + 1 + w0 + px;
    size_t off = (size_t)b*XREGB + (size_t)row*128u + (uint32_t)g*16u;
    *(uint4*)(g_xhi + off) = hv;
    *(uint4*)(g_xlo + off) = lv;
}

// aggregate + split weights: g_wp[b][tap]: rows 0-63 hi(oc), 64-127 lo(oc), 128B rows
__global__ __launch_bounds__(512)
void wprep_kernel(const float* __restrict__ weight) {
    int b = blockIdx.x, tap = blockIdx.y;
    int t = threadIdx.x;
    int oc = t >> 3, g = t & 7;
    float a0 = g_attn[b*KEXP+0], a1 = g_attn[b*KEXP+1],
          a2 = g_attn[b*KEXP+2], a3 = g_attn[b*KEXP+3];
    unsigned short hs[8], ls[8];
    #pragma unroll
    for (int j = 0; j < 8; j++) {
        int c = 8*g + j;
        size_t e = ((size_t)oc*C_ + c)*9 + tap;
        size_t stride = (size_t)OUT_*C_*9;
        float s = a0*weight[e] + a1*weight[e + stride] + a2*weight[e + 2*stride] + a3*weight[e + 3*stride];
        __nv_bfloat16 hb = __float2bfloat16_rn(s);
        float r = s - __bfloat162float(hb);
        hs[j] = __bfloat16_as_ushort(hb);
        ls[j] = __bfloat16_as_ushort(__float2bfloat16_rn(r));
    }
    uint4 hv, lv;
    hv.x = hs[0] | ((uint32_t)hs[1] << 16); hv.y = hs[2] | ((uint32_t)hs[3] << 16);
    hv.z = hs[4] | ((uint32_t)hs[5] << 16); hv.w = hs[6] | ((uint32_t)hs[7] << 16);
    lv.x = ls[0] | ((uint32_t)ls[1] << 16); lv.y = ls[2] | ((uint32_t)ls[3] << 16);
    lv.z = ls[4] | ((uint32_t)ls[5] << 16); lv.w = ls[6] | ((uint32_t)ls[7] << 16);
    size_t tb = ((size_t)b*9 + tap)*16384;
    *(uint4*)(g_wp + tb + (size_t)oc*128u + g*16u) = hv;
    *(uint4*)(g_wp + tb + (size_t)(64 + oc)*128u + g*16u) = lv;
}

// ================= conv: split-bf16 implicit GEMM on mma.sync =================
// CTA: 256 flat px x 64 oc, 16 warps (4m x 4n), warp tile 64 px x 16 oc
__global__ __launch_bounds__(512, 1)
void conv_mma_kernel(float* __restrict__ out) {
    extern __shared__ unsigned char smem[];
    uint32_t sb = smem_u32(smem);
    int tid = threadIdx.x, wid = tid >> 5, lane = tid & 31;
    int b = blockIdx.y;
    int n0 = 168 + blockIdx.x * MTILE;

    // ---- stage x strip (hi+lo) and W tap0 ----
    {
        const unsigned char* xs_h = g_xhi + (size_t)b*XREGB + (size_t)(XGUARD + n0 - 169)*128;
        const unsigned char* xs_l = g_xlo + (size_t)b*XREGB + (size_t)(XGUARD + n0 - 169)*128;
        for (int i = tid; i < STRIP*8; i += 512) {
            int r = i >> 3, c = i & 7;
            cp16(sb + OFF_XH + r*SROW_B + c*16, xs_h + (size_t)r*128 + c*16);
            cp16(sb + OFF_XL + r*SROW_B + c*16, xs_l + (size_t)r*128 + c*16);
        }
        const unsigned char* ws = g_wp + ((size_t)b*9 + 0)*16384;
        for (int i = tid; i < 128*8; i += 512) {
            int r = i >> 3, c = i & 7;
            cp16(sb + OFF_W + r*SROW_B + c*16, ws + (size_t)r*128 + c*16);
        }
        CP_COMMIT();
        CP_WAIT0();
        __syncthreads();
    }

    const int wm = (wid & 3) * 64;          // 64 px per warp (4 m16 tiles)
    const int wn = (wid >> 2) * 16;         // 16 oc per warp (2 n8 tiles)
    const int shifts[9] = {-169,-168,-167,-1,0,1,167,168,169};

    float acc[4][2][4];
    #pragma unroll
    for (int i = 0; i < 4; i++)
        #pragma unroll
        for (int j = 0; j < 2; j++)
            #pragma unroll
            for (int k = 0; k < 4; k++) acc[i][j][k] = 0.f;

    const uint32_t a_lane = (uint32_t)(lane & 15)*SROW_B + (uint32_t)(lane >> 4)*16;
    const uint32_t b_lane = (uint32_t)(lane & 7)*SROW_B + (uint32_t)((lane >> 3) & 1)*16;

    #pragma unroll
    for (int tap = 0; tap < 9; tap++) {
        // prefetch next tap's weights into the other buffer
        if (tap < 8) {
            const unsigned char* ws = g_wp + ((size_t)b*9 + tap + 1)*16384;
            uint32_t wdst = sb + OFF_W + ((tap + 1) & 1)*WBUF_SZ;
            for (int i = tid; i < 128*8; i += 512) {
                int r = i >> 3, c = i & 7;
                cp16(wdst + r*SROW_B + c*16, ws + (size_t)r*128 + c*16);
            }
            CP_COMMIT();
        }

        uint32_t wbuf = sb + OFF_W + (tap & 1)*WBUF_SZ;
        uint32_t xrow = sb + OFF_XH + (uint32_t)(169 + shifts[tap] + wm)*SROW_B + a_lane;

        #pragma unroll
        for (int ks = 0; ks < 4; ks++) {
            uint32_t kb = (uint32_t)ks*32;
            uint32_t bh[2][2], bl[2][2];
            #pragma unroll
            for (int ni = 0; ni < 2; ni++) {
                uint32_t ba = wbuf + (uint32_t)(wn + ni*8)*SROW_B + b_lane + kb;
                LDM2(bh[ni], ba);
                LDM2(bl[ni], ba + 64*SROW_B);
            }
            #pragma unroll
            for (int mi = 0; mi < 4; mi++) {
                uint32_t aa = xrow + (uint32_t)mi*(16*SROW_B) + kb;
                uint32_t ah[4], al[4];
                LDM4(ah, aa);
                LDM4(al, aa + (OFF_XL - OFF_XH));
                #pragma unroll
                for (int ni = 0; ni < 2; ni++) {
                    MMA16816(acc[mi][ni], ah, bh[ni]);
                    MMA16816(acc[mi][ni], ah, bl[ni]);
                    MMA16816(acc[mi][ni], al, bh[ni]);
                }
            }
        }
        if (tap < 8) { CP_WAIT0(); }
        __syncthreads();
    }

    // ---- epilogue: direct stores with padded-border filtering ----
    int g = lane >> 2, tc = lane & 3;
    #pragma unroll
    for (int mi = 0; mi < 4; mi++) {
        #pragma unroll
        for (int ni = 0; ni < 2; ni++) {
            int oc = wn + ni*8 + tc*2;
            float2 bias = *(const float2*)&g_aggb[b*OUT_ + oc];
            int pxA = n0 + wm + mi*16 + g;
            #pragma unroll
            for (int half = 0; half < 2; half++) {
                int px = pxA + half*8;
                int pr = px / PWROW;
                int c  = px - pr*PWROW;
                if (c >= 1 && c <= W_ && pr >= 1 && pr <= H_) {
                    size_t o = (((size_t)b*OUT_ + oc)*H_ + (pr - 1))*W_ + (c - 1);
                    out[o]      = acc[mi][ni][half*2 + 0] + bias.x;
                    out[o + HW] = acc[mi][ni][half*2 + 1] + bias.y;
                }
            }
        }
    }
}

extern "C" void kernel_launch(void* const* d_in, const int* in_sizes, int n_in,
                              void* d_out, int out_size) {
    const float* x      = (const float*)d_in[0];
    const float* fc1    = (const float*)d_in[1];
    const float* fc2    = (const float*)d_in[2];
    const float* weight = (const float*)d_in[3];
    const float* bias_p = (const float*)d_in[4];
    float* out = (float*)d_out;

    cudaFuncSetAttribute(conv_mma_kernel, cudaFuncAttributeMaxDynamicSharedMemorySize, DYN_SMEM);

    border_zero_kernel<<<B_, 256>>>();
    pool_kernel<<<B_*C_, 256>>>(x);
    attn_kernel<<<1, 32>>>(fc1, fc2, bias_p);
    xprep_kernel<<<dim3(H_, 5, B_), 256>>>(x);
    wprep_kernel<<<dim3(B_, 9), 512>>>(weight);
    conv_mma_kernel<<<dim3(NT_PER_B, B_), 512, DYN_SMEM>>>(out);
}

// round 8
// speedup vs baseline: 3.2563x; 1.2788x over previous
#include <cuda_runtime.h>
#include <cuda_fp16.h>
#include <stdint.h>
#include <math.h>

#define B_    16
#define C_    64
#define H_    160
#define W_    160
#define OUT_  64
#define KEXP  4
#define HID   17
#define TEMPR 34.0f
#define HW    25600

// ---- flat padded image: [b][px][64ch] fp16, 128B per pixel ----
#define PWROW   168
#define XGUARD  256
#define XPXTOT  27728                    // 256 + 162*168 + 256
#define XREGB   3549184ULL               // 27728*128
// ---- tiling ----
#define MTILE   512
#define NT_PER_B 53                      // ceil(26880/512)
#define STRIP   850                      // 512 + 2*169
#define SROW_B  144                      // padded smem row stride (bytes)
// ---- smem layout ----
#define OFF_X   0                        // 850*144 = 122400
#define OFF_W   122400
#define WBUF_SZ 18432                    // 128 rows * 144
#define DYN_SMEM 159264

__device__ __align__(128) unsigned char g_x[16*XREGB];
__device__ __align__(128) unsigned char g_wp[16*9*16384];   // [b][tap][row0-63 hi | 64-127 lo][128B]
__device__ float g_pooled[B_*C_];
__device__ float g_attn[B_*KEXP];
__device__ float g_aggb[B_*OUT_];

__device__ __forceinline__ uint32_t smem_u32(const void* p) {
    uint32_t a;
    asm("{ .reg .u64 t; cvta.to.shared.u64 t, %1; cvt.u32.u64 %0, t; }" : "=r"(a) : "l"(p));
    return a;
}
__device__ __forceinline__ void cp16(uint32_t dst, const void* src) {
    asm volatile("cp.async.cg.shared.global [%0], [%1], 16;" :: "r"(dst), "l"(src) : "memory");
}
#define CP_COMMIT() asm volatile("cp.async.commit_group;" ::: "memory")
#define CP_WAIT0()  asm volatile("cp.async.wait_group 0;" ::: "memory")

#define LDM4(r, a) \
    asm volatile("ldmatrix.sync.aligned.m8n8.x4.shared.b16 {%0,%1,%2,%3}, [%4];" \
        : "=r"((r)[0]), "=r"((r)[1]), "=r"((r)[2]), "=r"((r)[3]) : "r"(a))
#define MMA16816(d, a, b) \
    asm volatile("mma.sync.aligned.m16n8k16.row.col.f32.f16.f16.f32 " \
        "{%0,%1,%2,%3}, {%4,%5,%6,%7}, {%8,%9}, {%0,%1,%2,%3};" \
        : "+f"((d)[0]), "+f"((d)[1]), "+f"((d)[2]), "+f"((d)[3]) \
        : "r"((a)[0]), "r"((a)[1]), "r"((a)[2]), "r"((a)[3]), "r"((b)[0]), "r"((b)[1]))

// ================= preprocessing =================
// zero only the never-written guard/border pixel rows of g_x
__global__ void border_zero_kernel() {
    int b = blockIdx.x;
    size_t base = (size_t)b * XREGB;
    uint4 z = make_uint4(0,0,0,0);
    for (int i = threadIdx.x; i < 856*8; i += blockDim.x) {
        int r = i >> 3, c = i & 7;
        int row = (r < 425) ? r : (27297 + r - 425);
        *(uint4*)(g_x + base + (size_t)row*128u + (uint32_t)c*16u) = z;
    }
    for (int i = threadIdx.x; i < 159*8*8; i += blockDim.x) {
        int g  = i >> 6;
        int rr = (i >> 3) & 7;
        int c  = i & 7;
        int row = XGUARD + (g + 1)*PWROW + 161 + rr;
        *(uint4*)(g_x + base + (size_t)row*128u + (uint32_t)c*16u) = z;
    }
}

__global__ void pool_kernel(const float* __restrict__ x) {
    int bc = blockIdx.x;
    const float4* p = (const float4*)(x + (size_t)bc * HW);
    float s = 0.f;
    for (int i = threadIdx.x; i < HW/4; i += blockDim.x) {
        float4 v = p[i];
        s += (v.x + v.y) + (v.z + v.w);
    }
    #pragma unroll
    for (int o = 16; o; o >>= 1) s += __shfl_xor_sync(0xffffffffu, s, o);
    __shared__ float red[8];
    if ((threadIdx.x & 31) == 0) red[threadIdx.x >> 5] = s;
    __syncthreads();
    if (threadIdx.x == 0) {
        float t = 0.f;
        #pragma unroll
        for (int i = 0; i < 8; i++) t += red[i];
        g_pooled[bc] = t * (1.0f / (float)HW);
    }
}

__global__ void attn_kernel(const float* __restrict__ fc1,
                            const float* __restrict__ fc2,
                            const float* __restrict__ bias_p) {
    int b = threadIdx.x;
    if (b >= B_) return;
    float pooled[C_];
    #pragma unroll
    for (int c = 0; c < C_; c++) pooled[c] = g_pooled[b*C_ + c];
    float hid[HID];
    for (int j = 0; j < HID; j++) {
        float s = 0.f;
        #pragma unroll
        for (int c = 0; c < C_; c++) s += pooled[c] * fc1[j*C_ + c];
        hid[j] = fmaxf(s, 0.f);
    }
    float lg[KEXP];
    for (int k = 0; k < KEXP; k++) {
        float s = 0.f;
        #pragma unroll
        for (int j = 0; j < HID; j++) s += hid[j] * fc2[k*HID + j];
        lg[k] = s * (1.0f / TEMPR);
    }
    float m = fmaxf(fmaxf(lg[0], lg[1]), fmaxf(lg[2], lg[3]));
    float e[KEXP], sum = 0.f;
    for (int k = 0; k < KEXP; k++) { e[k] = expf(lg[k] - m); sum += e[k]; }
    float a[KEXP];
    for (int k = 0; k < KEXP; k++) { a[k] = e[k]/sum; g_attn[b*KEXP + k] = a[k]; }
    for (int o = 0; o < OUT_; o++) {
        float s = 0.f;
        #pragma unroll
        for (int k = 0; k < KEXP; k++) s += a[k] * bias_p[k*OUT_ + o];
        g_aggb[b*OUT_ + o] = s;
    }
}

// transpose x -> g_x (single fp16)
__global__ __launch_bounds__(256)
void xprep_kernel(const float* __restrict__ x) {
    __shared__ float s[64*33];
    int h  = blockIdx.x;
    int w0 = blockIdx.y * 32;
    int b  = blockIdx.z;
    int t  = threadIdx.x;
    int wd = t >> 5, lane = t & 31;
    #pragma unroll
    for (int i = 0; i < 8; i++) {
        int c = i*8 + wd;
        s[c*33 + lane] = x[(((size_t)b*C_ + c)*H_ + h)*W_ + w0 + lane];
    }
    __syncthreads();
    int px = t >> 3, g = t & 7;
    unsigned short hs[8];
    #pragma unroll
    for (int j = 0; j < 8; j++) {
        float v = s[(8*g + j)*33 + px];
        hs[j] = __half_as_ushort(__float2half_rn(v));
    }
    uint4 hv;
    hv.x = hs[0] | ((uint32_t)hs[1] << 16); hv.y = hs[2] | ((uint32_t)hs[3] << 16);
    hv.z = hs[4] | ((uint32_t)hs[5] << 16); hv.w = hs[6] | ((uint32_t)hs[7] << 16);
    uint32_t row = XGUARD + (h + 1)*PWROW + 1 + w0 + px;
    *(uint4*)(g_x + (size_t)b*XREGB + (size_t)row*128u + (uint32_t)g*16u) = hv;
}

// aggregate + fp16-split weights: rows 0-63 = hi(oc), rows 64-127 = lo(oc)
__global__ __launch_bounds__(512)
void wprep_kernel(const float* __restrict__ weight) {
    int b = blockIdx.x, tap = blockIdx.y;
    int t = threadIdx.x;
    int oc = t >> 3, g = t & 7;
    float a0 = g_attn[b*KEXP+0], a1 = g_attn[b*KEXP+1],
          a2 = g_attn[b*KEXP+2], a3 = g_attn[b*KEXP+3];
    unsigned short hs[8], ls[8];
    #pragma unroll
    for (int j = 0; j < 8; j++) {
        int c = 8*g + j;
        size_t e = ((size_t)oc*C_ + c)*9 + tap;
        size_t stride = (size_t)OUT_*C_*9;
        float s = a0*weight[e] + a1*weight[e + stride] + a2*weight[e + 2*stride] + a3*weight[e + 3*stride];
        __half hb = __float2half_rn(s);
        float r = s - __half2float(hb);
        hs[j] = __half_as_ushort(hb);
        ls[j] = __half_as_ushort(__float2half_rn(r));
    }
    uint4 hv, lv;
    hv.x = hs[0] | ((uint32_t)hs[1] << 16); hv.y = hs[2] | ((uint32_t)hs[3] << 16);
    hv.z = hs[4] | ((uint32_t)hs[5] << 16); hv.w = hs[6] | ((uint32_t)hs[7] << 16);
    lv.x = ls[0] | ((uint32_t)ls[1] << 16); lv.y = ls[2] | ((uint32_t)ls[3] << 16);
    lv.z = ls[4] | ((uint32_t)ls[5] << 16); lv.w = ls[6] | ((uint32_t)ls[7] << 16);
    size_t tb = ((size_t)b*9 + tap)*16384;
    *(uint4*)(g_wp + tb + (size_t)oc*128u + g*16u) = hv;
    *(uint4*)(g_wp + tb + (size_t)(64 + oc)*128u + g*16u) = lv;
}

// ================= conv: 2-pass fp16 implicit GEMM =================
// CTA: 512 px x 64 oc, 16 warps (8m x 2n), warp tile 64 px x 32 oc
__global__ __launch_bounds__(512, 1)
void conv_mma_kernel(float* __restrict__ out) {
    extern __shared__ unsigned char smem[];
    uint32_t sb = smem_u32(smem);
    int tid = threadIdx.x, wid = tid >> 5, lane = tid & 31;
    int b = blockIdx.y;
    int n0 = 168 + blockIdx.x * MTILE;

    // ---- stage x strip and W tap0 ----
    {
        const unsigned char* xs = g_x + (size_t)b*XREGB + (size_t)(XGUARD + n0 - 169)*128;
        for (int i = tid; i < STRIP*8; i += 512) {
            int r = i >> 3, c = i & 7;
            cp16(sb + OFF_X + r*SROW_B + c*16, xs + (size_t)r*128 + c*16);
        }
        const unsigned char* ws = g_wp + ((size_t)b*9 + 0)*16384;
        for (int i = tid; i < 128*8; i += 512) {
            int r = i >> 3, c = i & 7;
            cp16(sb + OFF_W + r*SROW_B + c*16, ws + (size_t)r*128 + c*16);
        }
        CP_COMMIT();
        CP_WAIT0();
        __syncthreads();
    }

    const int wm = (wid & 7) * 64;          // 64 px per warp (4 m16 tiles)
    const int wn = (wid >> 3) * 32;         // 32 oc per warp (4 n8 tiles)
    const int shifts[9] = {-169,-168,-167,-1,0,1,167,168,169};

    float acc[4][4][4];
    #pragma unroll
    for (int i = 0; i < 4; i++)
        #pragma unroll
        for (int j = 0; j < 4; j++)
            #pragma unroll
            for (int k = 0; k < 4; k++) acc[i][j][k] = 0.f;

    // A: m16k16 frag addresses (rows = pixels)
    const uint32_t a_lane = (uint32_t)(lane & 15)*SROW_B + (uint32_t)(lane >> 4)*16;
    // B: two-n8-tile x4 frag: lanes 0-7: oc+0..7 k0; 8-15: oc+0..7 k8; 16-23: oc+8..15 k0; 24-31: oc+8..15 k8
    const uint32_t b_lane = (uint32_t)((lane & 7) + ((lane >> 4) & 1)*8)*SROW_B
                          + (uint32_t)((lane >> 3) & 1)*16;

    #pragma unroll
    for (int tap = 0; tap < 9; tap++) {
        if (tap < 8) {
            const unsigned char* ws = g_wp + ((size_t)b*9 + tap + 1)*16384;
            uint32_t wdst = sb + OFF_W + ((tap + 1) & 1)*WBUF_SZ;
            for (int i = tid; i < 128*8; i += 512) {
                int r = i >> 3, c = i & 7;
                cp16(wdst + r*SROW_B + c*16, ws + (size_t)r*128 + c*16);
            }
            CP_COMMIT();
        }

        uint32_t wbuf = sb + OFF_W + (tap & 1)*WBUF_SZ;
        uint32_t xrow = sb + OFF_X + (uint32_t)(169 + shifts[tap] + wm)*SROW_B + a_lane;

        #pragma unroll
        for (int ks = 0; ks < 8; ks++) {
            uint32_t kb   = (uint32_t)(ks & 3)*32;       // 16 ch = 32 B
            uint32_t wrow = (uint32_t)(ks >> 2)*64;      // 0 = hi, 64 = lo
            uint32_t bf[2][4];
            #pragma unroll
            for (int nh = 0; nh < 2; nh++) {
                uint32_t ba = wbuf + (wrow + (uint32_t)(wn + nh*16))*SROW_B + b_lane + kb;
                LDM4(bf[nh], ba);
            }
            #pragma unroll
            for (int mi = 0; mi < 4; mi++) {
                uint32_t af[4];
                LDM4(af, xrow + (uint32_t)mi*(16*SROW_B) + kb);
                #pragma unroll
                for (int nh = 0; nh < 2; nh++) {
                    MMA16816(acc[mi][nh*2 + 0], af, (bf[nh] + 0));
                    MMA16816(acc[mi][nh*2 + 1], af, (bf[nh] + 2));
                }
            }
        }
        if (tap < 8) { CP_WAIT0(); }
        __syncthreads();
    }

    // ---- epilogue: direct stores with padded-border filtering ----
    int g = lane >> 2, tc = lane & 3;
    #pragma unroll
    for (int mi = 0; mi < 4; mi++) {
        #pragma unroll
        for (int ni = 0; ni < 4; ni++) {
            int oc = wn + ni*8 + tc*2;
            float2 bias = *(const float2*)&g_aggb[b*OUT_ + oc];
            int pxA = n0 + wm + mi*16 + g;
            #pragma unroll
            for (int half = 0; half < 2; half++) {
                int px = pxA + half*8;
                int pr = px / PWROW;
                int c  = px - pr*PWROW;
                if (c >= 1 && c <= W_ && pr >= 1 && pr <= H_) {
                    size_t o = (((size_t)b*OUT_ + oc)*H_ + (pr - 1))*W_ + (c - 1);
                    out[o]      = acc[mi][ni][half*2 + 0] + bias.x;
                    out[o + HW] = acc[mi][ni][half*2 + 1] + bias.y;
                }
            }
        }
    }
}

extern "C" void kernel_launch(void* const* d_in, const int* in_sizes, int n_in,
                              void* d_out, int out_size) {
    const float* x      = (const float*)d_in[0];
    const float* fc1    = (const float*)d_in[1];
    const float* fc2    = (const float*)d_in[2];
    const float* weight = (const float*)d_in[3];
    const float* bias_p = (const float*)d_in[4];
    float* out = (float*)d_out;

    cudaFuncSetAttribute(conv_mma_kernel, cudaFuncAttributeMaxDynamicSharedMemorySize, DYN_SMEM);

    border_zero_kernel<<<B_, 256>>>();
    pool_kernel<<<B_*C_, 256>>>(x);
    attn_kernel<<<1, 32>>>(fc1, fc2, bias_p);
    xprep_kernel<<<dim3(H_, 5, B_), 256>>>(x);
    wprep_kernel<<<dim3(B_, 9), 512>>>(weight);
    conv_mma_kernel<<<dim3(NT_PER_B, B_), 512, DYN_SMEM>>>(out);
}

// round 10
// speedup vs baseline: 4.5804x; 1.4066x over previous
#include <cuda_runtime.h>
#include <cuda_fp16.h>
#include <stdint.h>
#include <math.h>

#define B_    16
#define C_    64
#define H_    160
#define W_    160
#define OUT_  64
#define KEXP  4
#define HID   17
#define TEMPR 34.0f
#define HW    25600

// ---- flat padded image: [b][px][64ch] fp16, 128B per pixel ----
#define PWROW   168
#define XGUARD  256
#define XPXTOT  27728                    // 256 + 162*168 + 256
#define XREGB   3549184ULL               // 27728*128
// ---- tiling ----
#define MTILE   512
#define NT_PER_B 53                      // ceil(26880/512)
#define STRIP   850                      // 512 + 2*169
#define SROW_B  144                      // padded smem row stride (bytes)
// ---- smem layout ----
#define OFF_X   0                        // 850*144 = 122400
#define OFF_W   122400
#define WBUF_SZ 9216                     // 64 rows * 144
#define DYN_SMEM 140832

__device__ __align__(128) unsigned char g_x[16*XREGB];
__device__ __align__(128) unsigned char g_wp[16*9*8192];    // [b][tap][64 oc rows][128B]
__device__ float g_pooled[B_*C_];
__device__ float g_attn[B_*KEXP];
__device__ float g_aggb[B_*OUT_];

__device__ __forceinline__ uint32_t smem_u32(const void* p) {
    uint32_t a;
    asm("{ .reg .u64 t; cvta.to.shared.u64 t, %1; cvt.u32.u64 %0, t; }" : "=r"(a) : "l"(p));
    return a;
}
__device__ __forceinline__ void cp16(uint32_t dst, const void* src) {
    asm volatile("cp.async.cg.shared.global [%0], [%1], 16;" :: "r"(dst), "l"(src) : "memory");
}
#define CP_COMMIT() asm volatile("cp.async.commit_group;" ::: "memory")
#define CP_WAIT0()  asm volatile("cp.async.wait_group 0;" ::: "memory")

#define LDM4(r, a) \
    asm volatile("ldmatrix.sync.aligned.m8n8.x4.shared.b16 {%0,%1,%2,%3}, [%4];" \
        : "=r"((r)[0]), "=r"((r)[1]), "=r"((r)[2]), "=r"((r)[3]) : "r"(a))
#define MMA16816(d, a, b) \
    asm volatile("mma.sync.aligned.m16n8k16.row.col.f32.f16.f16.f32 " \
        "{%0,%1,%2,%3}, {%4,%5,%6,%7}, {%8,%9}, {%0,%1,%2,%3};" \
        : "+f"((d)[0]), "+f"((d)[1]), "+f"((d)[2]), "+f"((d)[3]) \
        : "r"((a)[0]), "r"((a)[1]), "r"((a)[2]), "r"((a)[3]), "r"((b)[0]), "r"((b)[1]))

// ================= preprocessing =================
// zero only the never-written guard/border pixel rows of g_x
__global__ void border_zero_kernel() {
    int b = blockIdx.x;
    size_t base = (size_t)b * XREGB;
    uint4 z = make_uint4(0,0,0,0);
    for (int i = threadIdx.x; i < 856*8; i += blockDim.x) {
        int r = i >> 3, c = i & 7;
        int row = (r < 425) ? r : (27297 + r - 425);
        *(uint4*)(g_x + base + (size_t)row*128u + (uint32_t)c*16u) = z;
    }
    for (int i = threadIdx.x; i < 159*8*8; i += blockDim.x) {
        int g  = i >> 6;
        int rr = (i >> 3) & 7;
        int c  = i & 7;
        int row = XGUARD + (g + 1)*PWROW + 161 + rr;
        *(uint4*)(g_x + base + (size_t)row*128u + (uint32_t)c*16u) = z;
    }
}

__global__ void pool_kernel(const float* __restrict__ x) {
    int bc = blockIdx.x;
    const float4* p = (const float4*)(x + (size_t)bc * HW);
    float s = 0.f;
    for (int i = threadIdx.x; i < HW/4; i += blockDim.x) {
        float4 v = p[i];
        s += (v.x + v.y) + (v.z + v.w);
    }
    #pragma unroll
    for (int o = 16; o; o >>= 1) s += __shfl_xor_sync(0xffffffffu, s, o);
    __shared__ float red[8];
    if ((threadIdx.x & 31) == 0) red[threadIdx.x >> 5] = s;
    __syncthreads();
    if (threadIdx.x == 0) {
        float t = 0.f;
        #pragma unroll
        for (int i = 0; i < 8; i++) t += red[i];
        g_pooled[bc] = t * (1.0f / (float)HW);
    }
}

__global__ void attn_kernel(const float* __restrict__ fc1,
                            const float* __restrict__ fc2,
                            const float* __restrict__ bias_p) {
    int b = threadIdx.x;
    if (b >= B_) return;
    float pooled[C_];
    #pragma unroll
    for (int c = 0; c < C_; c++) pooled[c] = g_pooled[b*C_ + c];
    float hid[HID];
    for (int j = 0; j < HID; j++) {
        float s = 0.f;
        #pragma unroll
        for (int c = 0; c < C_; c++) s += pooled[c] * fc1[j*C_ + c];
        hid[j] = fmaxf(s, 0.f);
    }
    float lg[KEXP];
    for (int k = 0; k < KEXP; k++) {
        float s = 0.f;
        #pragma unroll
        for (int j = 0; j < HID; j++) s += hid[j] * fc2[k*HID + j];
        lg[k] = s * (1.0f / TEMPR);
    }
    float m = fmaxf(fmaxf(lg[0], lg[1]), fmaxf(lg[2], lg[3]));
    float e[KEXP], sum = 0.f;
    for (int k = 0; k < KEXP; k++) { e[k] = expf(lg[k] - m); sum += e[k]; }
    float a[KEXP];
    for (int k = 0; k < KEXP; k++) { a[k] = e[k]/sum; g_attn[b*KEXP + k] = a[k]; }
    for (int o = 0; o < OUT_; o++) {
        float s = 0.f;
        #pragma unroll
        for (int k = 0; k < KEXP; k++) s += a[k] * bias_p[k*OUT_ + o];
        g_aggb[b*OUT_ + o] = s;
    }
}

// transpose x -> g_x (single fp16)
__global__ __launch_bounds__(256)
void xprep_kernel(const float* __restrict__ x) {
    __shared__ float s[64*33];
    int h  = blockIdx.x;
    int w0 = blockIdx.y * 32;
    int b  = blockIdx.z;
    int t  = threadIdx.x;
    int wd = t >> 5, lane = t & 31;
    #pragma unroll
    for (int i = 0; i < 8; i++) {
        int c = i*8 + wd;
        s[c*33 + lane] = x[(((size_t)b*C_ + c)*H_ + h)*W_ + w0 + lane];
    }
    __syncthreads();
    int px = t >> 3, g = t & 7;
    unsigned short hs[8];
    #pragma unroll
    for (int j = 0; j < 8; j++) {
        float v = s[(8*g + j)*33 + px];
        hs[j] = __half_as_ushort(__float2half_rn(v));
    }
    uint4 hv;
    hv.x = hs[0] | ((uint32_t)hs[1] << 16); hv.y = hs[2] | ((uint32_t)hs[3] << 16);
    hv.z = hs[4] | ((uint32_t)hs[5] << 16); hv.w = hs[6] | ((uint32_t)hs[7] << 16);
    uint32_t row = XGUARD + (h + 1)*PWROW + 1 + w0 + px;
    *(uint4*)(g_x + (size_t)b*XREGB + (size_t)row*128u + (uint32_t)g*16u) = hv;
}

// aggregate + fp16 weights (single precision pass): 64 oc rows of 128B
__global__ __launch_bounds__(512)
void wprep_kernel(const float* __restrict__ weight) {
    int b = blockIdx.x, tap = blockIdx.y;
    int t = threadIdx.x;
    int oc = t >> 3, g = t & 7;
    float a0 = g_attn[b*KEXP+0], a1 = g_attn[b*KEXP+1],
          a2 = g_attn[b*KEXP+2], a3 = g_attn[b*KEXP+3];
    unsigned short hs[8];
    #pragma unroll
    for (int j = 0; j < 8; j++) {
        int c = 8*g + j;
        size_t e = ((size_t)oc*C_ + c)*9 + tap;
        size_t stride = (size_t)OUT_*C_*9;
        float s = a0*weight[e] + a1*weight[e + stride] + a2*weight[e + 2*stride] + a3*weight[e + 3*stride];
        hs[j] = __half_as_ushort(__float2half_rn(s));
    }
    uint4 hv;
    hv.x = hs[0] | ((uint32_t)hs[1] << 16); hv.y = hs[2] | ((uint32_t)hs[3] << 16);
    hv.z = hs[4] | ((uint32_t)hs[5] << 16); hv.w = hs[6] | ((uint32_t)hs[7] << 16);
    size_t tb = ((size_t)b*9 + tap)*8192;
    *(uint4*)(g_wp + tb + (size_t)oc*128u + g*16u) = hv;
}

// ================= conv: single-pass fp16 implicit GEMM =================
// CTA: 512 px x 64 oc, 16 warps (8m x 2n), warp tile 64 px x 32 oc
__global__ __launch_bounds__(512, 1)
void conv_mma_kernel(float* __restrict__ out) {
    extern __shared__ unsigned char smem[];
    uint32_t sb = smem_u32(smem);
    int tid = threadIdx.x, wid = tid >> 5, lane = tid & 31;
    int b = blockIdx.y;
    int n0 = 168 + blockIdx.x * MTILE;

    // ---- stage x strip and W tap0 ----
    {
        const unsigned char* xs = g_x + (size_t)b*XREGB + (size_t)(XGUARD + n0 - 169)*128;
        for (int i = tid; i < STRIP*8; i += 512) {
            int r = i >> 3, c = i & 7;
            cp16(sb + OFF_X + r*SROW_B + c*16, xs + (size_t)r*128 + c*16);
        }
        const unsigned char* ws = g_wp + ((size_t)b*9 + 0)*8192;
        for (int i = tid; i < 64*8; i += 512) {
            int r = i >> 3, c = i & 7;
            cp16(sb + OFF_W + r*SROW_B + c*16, ws + (size_t)r*128 + c*16);
        }
        CP_COMMIT();
        CP_WAIT0();
        __syncthreads();
    }

    const int wm = (wid & 7) * 64;          // 64 px per warp (4 m16 tiles)
    const int wn = (wid >> 3) * 32;         // 32 oc per warp (4 n8 tiles)
    const int shifts[9] = {-169,-168,-167,-1,0,1,167,168,169};

    float acc[4][4][4];
    #pragma unroll
    for (int i = 0; i < 4; i++)
        #pragma unroll
        for (int j = 0; j < 4; j++)
            #pragma unroll
            for (int k = 0; k < 4; k++) acc[i][j][k] = 0.f;

    // A: m16k16 frag addresses (rows = pixels)
    const uint32_t a_lane = (uint32_t)(lane & 15)*SROW_B + (uint32_t)(lane >> 4)*16;
    // B x4 frag covering two n8 tiles: lanes 0-7: oc+0..7 k0; 8-15: k8; 16-23: oc+8..15 k0; 24-31: k8
    const uint32_t b_lane = (uint32_t)((lane & 7) + ((lane >> 4) & 1)*8)*SROW_B
                          + (uint32_t)((lane >> 3) & 1)*16;

    #pragma unroll
    for (int tap = 0; tap < 9; tap++) {
        if (tap < 8) {
            const unsigned char* ws = g_wp + ((size_t)b*9 + tap + 1)*8192;
            uint32_t wdst = sb + OFF_W + ((tap + 1) & 1)*WBUF_SZ;
            for (int i = tid; i < 64*8; i += 512) {
                int r = i >> 3, c = i & 7;
                cp16(wdst + r*SROW_B + c*16, ws + (size_t)r*128 + c*16);
            }
            CP_COMMIT();
        }

        uint32_t wbuf = sb + OFF_W + (tap & 1)*WBUF_SZ;
        uint32_t xrow = sb + OFF_X + (uint32_t)(169 + shifts[tap] + wm)*SROW_B + a_lane;

        #pragma unroll
        for (int ks = 0; ks < 4; ks++) {
            uint32_t kb = (uint32_t)ks*32;               // 16 ch = 32 B
            uint32_t bf[2][4];
            #pragma unroll
            for (int nh = 0; nh < 2; nh++) {
                uint32_t ba = wbuf + (uint32_t)(wn + nh*16)*SROW_B + b_lane + kb;
                LDM4(bf[nh], ba);
            }
            #pragma unroll
            for (int mi = 0; mi < 4; mi++) {
                uint32_t af[4];
                LDM4(af, xrow + (uint32_t)mi*(16*SROW_B) + kb);
                #pragma unroll
                for (int nh = 0; nh < 2; nh++) {
                    MMA16816(acc[mi][nh*2 + 0], af, (bf[nh] + 0));
                    MMA16816(acc[mi][nh*2 + 1], af, (bf[nh] + 2));
                }
            }
        }
        if (tap < 8) { CP_WAIT0(); }
        __syncthreads();
    }

    // ---- epilogue: direct stores with padded-border filtering ----
    int g = lane >> 2, tc = lane & 3;
    #pragma unroll
    for (int mi = 0; mi < 4; mi++) {
        #pragma unroll
        for (int ni = 0; ni < 4; ni++) {
            int oc = wn + ni*8 + tc*2;
            float2 bias = *(const float2*)&g_aggb[b*OUT_ + oc];
            int pxA = n0 + wm + mi*16 + g;
            #pragma unroll
            for (int half = 0; half < 2; half++) {
                int px = pxA + half*8;
                int pr = px / PWROW;
                int c  = px - pr*PWROW;
                if (c >= 1 && c <= W_ && pr >= 1 && pr <= H_) {
                    size_t o = (((size_t)b*OUT_ + oc)*H_ + (pr - 1))*W_ + (c - 1);
                    out[o]      = acc[mi][ni][half*2 + 0] + bias.x;
                    out[o + HW] = acc[mi][ni][half*2 + 1] + bias.y;
                }
            }
        }
    }
}

extern "C" void kernel_launch(void* const* d_in, const int* in_sizes, int n_in,
                              void* d_out, int out_size) {
    const float* x      = (const float*)d_in[0];
    const float* fc1    = (const float*)d_in[1];
    const float* fc2    = (const float*)d_in[2];
    const float* weight = (const float*)d_in[3];
    const float* bias_p = (const float*)d_in[4];
    float* out = (float*)d_out;

    cudaFuncSetAttribute(conv_mma_kernel, cudaFuncAttributeMaxDynamicSharedMemorySize, DYN_SMEM);

    border_zero_kernel<<<B_, 256>>>();
    pool_kernel<<<B_*C_, 256>>>(x);
    attn_kernel<<<1, 32>>>(fc1, fc2, bias_p);
    xprep_kernel<<<dim3(H_, 5, B_), 256>>>(x);
    wprep_kernel<<<dim3(B_, 9), 512>>>(weight);
    conv_mma_kernel<<<dim3(NT_PER_B, B_), 512, DYN_SMEM>>>(out);
}

// round 11
// speedup vs baseline: 4.7268x; 1.0320x over previous
#include <cuda_runtime.h>
#include <cuda_fp16.h>
#include <stdint.h>
#include <math.h>

#define B_    16
#define C_    64
#define H_    160
#define W_    160
#define OUT_  64
#define KEXP  4
#define HID   17
#define TEMPR 34.0f
#define HW    25600

// ---- flat padded image: [b][px][64ch] fp16, 128B per pixel ----
#define PWROW   168
#define XGUARD  256
#define XREGB   3549184ULL               // 27728*128
// ---- tiling ----
#define MTILE   512
#define NT_PER_B 53                      // ceil(26880/512)
#define STRIP   850                      // 512 + 2*169
#define SROW_B  144                      // padded smem row stride (bytes)
// ---- smem layout: x strip + ALL 9 taps of weights ----
#define OFF_X   0                        // 850*144 = 122400
#define OFF_W   122400
#define WBUF_SZ 9216                     // 64 rows * 144
#define DYN_SMEM 205344                  // 122400 + 9*9216

__device__ __align__(128) unsigned char g_x[16*XREGB];
__device__ __align__(128) unsigned char g_wp[16*9*8192];    // [b][tap][64 oc rows][128B]
__device__ float g_pooled[B_*C_];
__device__ float g_attn[B_*KEXP];
__device__ float g_aggb[B_*OUT_];

__device__ __forceinline__ uint32_t smem_u32(const void* p) {
    uint32_t a;
    asm("{ .reg .u64 t; cvta.to.shared.u64 t, %1; cvt.u32.u64 %0, t; }" : "=r"(a) : "l"(p));
    return a;
}
__device__ __forceinline__ void cp16(uint32_t dst, const void* src) {
    asm volatile("cp.async.cg.shared.global [%0], [%1], 16;" :: "r"(dst), "l"(src) : "memory");
}
#define CP_COMMIT() asm volatile("cp.async.commit_group;" ::: "memory")
#define CP_WAIT0()  asm volatile("cp.async.wait_group 0;" ::: "memory")

#define LDM4(r, a) \
    asm volatile("ldmatrix.sync.aligned.m8n8.x4.shared.b16 {%0,%1,%2,%3}, [%4];" \
        : "=r"((r)[0]), "=r"((r)[1]), "=r"((r)[2]), "=r"((r)[3]) : "r"(a))
#define MMA16816(d, a, b) \
    asm volatile("mma.sync.aligned.m16n8k16.row.col.f32.f16.f16.f32 " \
        "{%0,%1,%2,%3}, {%4,%5,%6,%7}, {%8,%9}, {%0,%1,%2,%3};" \
        : "+f"((d)[0]), "+f"((d)[1]), "+f"((d)[2]), "+f"((d)[3]) \
        : "r"((a)[0]), "r"((a)[1]), "r"((a)[2]), "r"((a)[3]), "r"((b)[0]), "r"((b)[1]))

// ================= preprocessing =================
// zero guard/border rows of g_x + zero g_pooled accumulators
__global__ void border_zero_kernel() {
    int b = blockIdx.x;
    size_t base = (size_t)b * XREGB;
    uint4 z = make_uint4(0,0,0,0);
    for (int i = threadIdx.x; i < 856*8; i += blockDim.x) {
        int r = i >> 3, c = i & 7;
        int row = (r < 425) ? r : (27297 + r - 425);
        *(uint4*)(g_x + base + (size_t)row*128u + (uint32_t)c*16u) = z;
    }
    for (int i = threadIdx.x; i < 159*8*8; i += blockDim.x) {
        int g  = i >> 6;
        int rr = (i >> 3) & 7;
        int c  = i & 7;
        int row = XGUARD + (g + 1)*PWROW + 161 + rr;
        *(uint4*)(g_x + base + (size_t)row*128u + (uint32_t)c*16u) = z;
    }
    // zero pooled accumulators (re-run every launch: deterministic)
    for (int i = threadIdx.x; i < C_; i += blockDim.x)
        g_pooled[b*C_ + i] = 0.f;
}

__global__ void attn_kernel(const float* __restrict__ fc1,
                            const float* __restrict__ fc2,
                            const float* __restrict__ bias_p) {
    int b = threadIdx.x;
    if (b >= B_) return;
    float pooled[C_];
    #pragma unroll
    for (int c = 0; c < C_; c++) pooled[c] = g_pooled[b*C_ + c] * (1.0f / (float)HW);
    float hid[HID];
    for (int j = 0; j < HID; j++) {
        float s = 0.f;
        #pragma unroll
        for (int c = 0; c < C_; c++) s += pooled[c] * fc1[j*C_ + c];
        hid[j] = fmaxf(s, 0.f);
    }
    float lg[KEXP];
    for (int k = 0; k < KEXP; k++) {
        float s = 0.f;
        #pragma unroll
        for (int j = 0; j < HID; j++) s += hid[j] * fc2[k*HID + j];
        lg[k] = s * (1.0f / TEMPR);
    }
    float m = fmaxf(fmaxf(lg[0], lg[1]), fmaxf(lg[2], lg[3]));
    float e[KEXP], sum = 0.f;
    for (int k = 0; k < KEXP; k++) { e[k] = expf(lg[k] - m); sum += e[k]; }
    float a[KEXP];
    for (int k = 0; k < KEXP; k++) { a[k] = e[k]/sum; g_attn[b*KEXP + k] = a[k]; }
    for (int o = 0; o < OUT_; o++) {
        float s = 0.f;
        #pragma unroll
        for (int k = 0; k < KEXP; k++) s += a[k] * bias_p[k*OUT_ + o];
        g_aggb[b*OUT_ + o] = s;
    }
}

// transpose x -> g_x (fp16) + fused global-average-pool partial sums
__global__ __launch_bounds__(256)
void xprep_kernel(const float* __restrict__ x) {
    __shared__ float s[64*33];
    int h  = blockIdx.x;
    int w0 = blockIdx.y * 32;
    int b  = blockIdx.z;
    int t  = threadIdx.x;
    int wd = t >> 5, lane = t & 31;
    #pragma unroll
    for (int i = 0; i < 8; i++) {
        int c = i*8 + wd;
        s[c*33 + lane] = x[(((size_t)b*C_ + c)*H_ + h)*W_ + w0 + lane];
    }
    __syncthreads();
    int px = t >> 3, g = t & 7;
    unsigned short hs[8];
    #pragma unroll
    for (int j = 0; j < 8; j++) {
        float v = s[(8*g + j)*33 + px];
        hs[j] = __half_as_ushort(__float2half_rn(v));
    }
    uint4 hv;
    hv.x = hs[0] | ((uint32_t)hs[1] << 16); hv.y = hs[2] | ((uint32_t)hs[3] << 16);
    hv.z = hs[4] | ((uint32_t)hs[5] << 16); hv.w = hs[6] | ((uint32_t)hs[7] << 16);
    uint32_t row = XGUARD + (h + 1)*PWROW + 1 + w0 + px;
    *(uint4*)(g_x + (size_t)b*XREGB + (size_t)row*128u + (uint32_t)g*16u) = hv;

    // fused pool: threads 0-63 each reduce 32 px of one channel
    if (t < 64) {
        float sum = 0.f;
        #pragma unroll
        for (int p = 0; p < 32; p++) sum += s[t*33 + p];
        atomicAdd(&g_pooled[b*C_ + t], sum);
    }
}

// aggregate + fp16 weights: 64 oc rows of 128B per (b, tap)
__global__ __launch_bounds__(512)
void wprep_kernel(const float* __restrict__ weight) {
    int b = blockIdx.x, tap = blockIdx.y;
    int t = threadIdx.x;
    int oc = t >> 3, g = t & 7;
    float a0 = g_attn[b*KEXP+0], a1 = g_attn[b*KEXP+1],
          a2 = g_attn[b*KEXP+2], a3 = g_attn[b*KEXP+3];
    unsigned short hs[8];
    #pragma unroll
    for (int j = 0; j < 8; j++) {
        int c = 8*g + j;
        size_t e = ((size_t)oc*C_ + c)*9 + tap;
        size_t stride = (size_t)OUT_*C_*9;
        float s = a0*weight[e] + a1*weight[e + stride] + a2*weight[e + 2*stride] + a3*weight[e + 3*stride];
        hs[j] = __half_as_ushort(__float2half_rn(s));
    }
    uint4 hv;
    hv.x = hs[0] | ((uint32_t)hs[1] << 16); hv.y = hs[2] | ((uint32_t)hs[3] << 16);
    hv.z = hs[4] | ((uint32_t)hs[5] << 16); hv.w = hs[6] | ((uint32_t)hs[7] << 16);
    size_t tb = ((size_t)b*9 + tap)*8192;
    *(uint4*)(g_wp + tb + (size_t)oc*128u + g*16u) = hv;
}

// ================= conv: single-pass fp16 implicit GEMM, sync-free mainloop =================
// CTA: 512 px x 64 oc, 16 warps (8m x 2n), warp tile 64 px x 32 oc.
// All 9 taps of weights preloaded -> after one initial barrier the mainloop
// is pure LDSM+HMMA with no __syncthreads / cp.async waits.
__global__ __launch_bounds__(512, 1)
void conv_mma_kernel(float* __restrict__ out) {
    extern __shared__ unsigned char smem[];
    uint32_t sb = smem_u32(smem);
    int tid = threadIdx.x, wid = tid >> 5, lane = tid & 31;
    int b = blockIdx.y;
    int n0 = 168 + blockIdx.x * MTILE;

    // ---- stage x strip + ALL 9 weight taps ----
    {
        const unsigned char* xs = g_x + (size_t)b*XREGB + (size_t)(XGUARD + n0 - 169)*128;
        for (int i = tid; i < STRIP*8; i += 512) {
            int r = i >> 3, c = i & 7;
            cp16(sb + OFF_X + r*SROW_B + c*16, xs + (size_t)r*128 + c*16);
        }
        const unsigned char* ws = g_wp + (size_t)b*9*8192;
        for (int i = tid; i < 9*64*8; i += 512) {
            int tap = i / (64*8);
            int r   = (i >> 3) & 63;
            int c   = i & 7;
            cp16(sb + OFF_W + tap*WBUF_SZ + r*SROW_B + c*16,
                 ws + (size_t)tap*8192 + (size_t)r*128 + c*16);
        }
        CP_COMMIT();
        CP_WAIT0();
        __syncthreads();
    }

    const int wm = (wid & 7) * 64;          // 64 px per warp (4 m16 tiles)
    const int wn = (wid >> 3) * 32;         // 32 oc per warp (4 n8 tiles)
    const int shifts[9] = {-169,-168,-167,-1,0,1,167,168,169};

    float acc[4][4][4];
    #pragma unroll
    for (int i = 0; i < 4; i++)
        #pragma unroll
        for (int j = 0; j < 4; j++)
            #pragma unroll
            for (int k = 0; k < 4; k++) acc[i][j][k] = 0.f;

    const uint32_t a_lane = (uint32_t)(lane & 15)*SROW_B + (uint32_t)(lane >> 4)*16;
    const uint32_t b_lane = (uint32_t)((lane & 7) + ((lane >> 4) & 1)*8)*SROW_B
                          + (uint32_t)((lane >> 3) & 1)*16;

    #pragma unroll
    for (int tap = 0; tap < 9; tap++) {
        uint32_t wbuf = sb + OFF_W + (uint32_t)tap*WBUF_SZ;
        uint32_t xrow = sb + OFF_X + (uint32_t)(169 + shifts[tap] + wm)*SROW_B + a_lane;

        #pragma unroll
        for (int ks = 0; ks < 4; ks++) {
            uint32_t kb = (uint32_t)ks*32;               // 16 ch = 32 B
            uint32_t bf[2][4];
            #pragma unroll
            for (int nh = 0; nh < 2; nh++) {
                uint32_t ba = wbuf + (uint32_t)(wn + nh*16)*SROW_B + b_lane + kb;
                LDM4(bf[nh], ba);
            }
            #pragma unroll
            for (int mi = 0; mi < 4; mi++) {
                uint32_t af[4];
                LDM4(af, xrow + (uint32_t)mi*(16*SROW_B) + kb);
                #pragma unroll
                for (int nh = 0; nh < 2; nh++) {
                    MMA16816(acc[mi][nh*2 + 0], af, (bf[nh] + 0));
                    MMA16816(acc[mi][nh*2 + 1], af, (bf[nh] + 2));
                }
            }
        }
    }

    // ---- epilogue: direct stores with padded-border filtering ----
    int g = lane >> 2, tc = lane & 3;
    #pragma unroll
    for (int mi = 0; mi < 4; mi++) {
        #pragma unroll
        for (int ni = 0; ni < 4; ni++) {
            int oc = wn + ni*8 + tc*2;
            float2 bias = *(const float2*)&g_aggb[b*OUT_ + oc];
            int pxA = n0 + wm + mi*16 + g;
            #pragma unroll
            for (int half = 0; half < 2; half++) {
                int px = pxA + half*8;
                int pr = px / PWROW;
                int c  = px - pr*PWROW;
                if (c >= 1 && c <= W_ && pr >= 1 && pr <= H_) {
                    size_t o = (((size_t)b*OUT_ + oc)*H_ + (pr - 1))*W_ + (c - 1);
                    out[o]      = acc[mi][ni][half*2 + 0] + bias.x;
                    out[o + HW] = acc[mi][ni][half*2 + 1] + bias.y;
                }
            }
        }
    }
}

extern "C" void kernel_launch(void* const* d_in, const int* in_sizes, int n_in,
                              void* d_out, int out_size) {
    const float* x      = (const float*)d_in[0];
    const float* fc1    = (const float*)d_in[1];
    const float* fc2    = (const float*)d_in[2];
    const float* weight = (const float*)d_in[3];
    const float* bias_p = (const float*)d_in[4];
    float* out = (float*)d_out;

    cudaFuncSetAttribute(conv_mma_kernel, cudaFuncAttributeMaxDynamicSharedMemorySize, DYN_SMEM);

    border_zero_kernel<<<B_, 256>>>();
    xprep_kernel<<<dim3(H_, 5, B_), 256>>>(x);
    attn_kernel<<<1, 32>>>(fc1, fc2, bias_p);
    wprep_kernel<<<dim3(B_, 9), 512>>>(weight);
    conv_mma_kernel<<<dim3(NT_PER_B, B_), 512, DYN_SMEM>>>(out);
}

// round 13
// speedup vs baseline: 5.8021x; 1.2275x over previous
#include <cuda_runtime.h>
#include <cuda_fp16.h>
#include <stdint.h>
#include <math.h>

#define B_    16
#define C_    64
#define H_    160
#define W_    160
#define OUT_  64
#define KEXP  4
#define HID   17
#define TEMPR 34.0f
#define HW    25600

// ---- flat padded image: [b][flat_px][64ch] fp16, 128B per pixel ----
// flat n = h*161 + w ; single shared zero cell between rows (w==160 junction)
#define PW      161
#define XGF     192                      // front guard rows (zeroed)
#define NPOS    25759                    // 159*161+159+1 output positions
#define XROWS   26496                    // XGF + 26304 (covers all strip reads)
#define XREGB   3391488ULL               // 26496*128
// ---- tiling ----
#define MTILE   512
#define NT_PER_B 51                      // ceil(25759/512)
#define STRIP   840                      // 512 + 2*162 + pad
#define SROW_B  144                      // padded smem row stride (bytes)
// ---- smem layout: x strip + ALL 9 weight taps ----
#define OFF_X   0                        // 840*144 = 120960
#define OFF_W   120960
#define WBUF_SZ 9216                     // 64 rows * 144
#define DYN_SMEM 203904                  // 120960 + 9*9216

__device__ __align__(128) unsigned char g_x[16*XREGB];
__device__ __align__(128) unsigned char g_wp[16*9*8192];    // [b][tap][64 oc rows][128B]
__device__ float g_pooled[B_*C_];
__device__ float g_aggb[B_*OUT_];

__device__ __forceinline__ uint32_t smem_u32(const void* p) {
    uint32_t a;
    asm("{ .reg .u64 t; cvta.to.shared.u64 t, %1; cvt.u32.u64 %0, t; }" : "=r"(a) : "l"(p));
    return a;
}
__device__ __forceinline__ void cp16(uint32_t dst, const void* src) {
    asm volatile("cp.async.cg.shared.global [%0], [%1], 16;" :: "r"(dst), "l"(src) : "memory");
}
#define CP_COMMIT() asm volatile("cp.async.commit_group;" ::: "memory")
#define CP_WAIT0()  asm volatile("cp.async.wait_group 0;" ::: "memory")

#define LDM4(r, a) \
    asm volatile("ldmatrix.sync.aligned.m8n8.x4.shared.b16 {%0,%1,%2,%3}, [%4];" \
        : "=r"((r)[0]), "=r"((r)[1]), "=r"((r)[2]), "=r"((r)[3]) : "r"(a))
#define MMA16816(d, a, b) \
    asm volatile("mma.sync.aligned.m16n8k16.row.col.f32.f16.f16.f32 " \
        "{%0,%1,%2,%3}, {%4,%5,%6,%7}, {%8,%9}, {%0,%1,%2,%3};" \
        : "+f"((d)[0]), "+f"((d)[1]), "+f"((d)[2]), "+f"((d)[3]) \
        : "r"((a)[0]), "r"((a)[1]), "r"((a)[2]), "r"((a)[3]), "r"((b)[0]), "r"((b)[1]))

// ================= preprocessing =================
// zero guard rows, junction cells, and g_pooled. 896 rows per batch, split 8 ways:
//   ri<192         : front guard row ri
//   192<=ri<737    : back guard row 25951 + (ri-192)   (545 rows)
//   737<=ri<896    : junction row XGF + h*161 + 160, h = ri-737   (159 rows)
__global__ void border_zero_kernel() {
    int b  = blockIdx.x;
    int gy = blockIdx.y;                     // 0..7
    size_t base = (size_t)b * XREGB;
    uint4 z = make_uint4(0,0,0,0);
    for (int i = gy*896 + threadIdx.x; i < (gy + 1)*896; i += blockDim.x) {
        int ri = i >> 3, c = i & 7;
        int row;
        if (ri < 192)      row = ri;
        else if (ri < 737) row = 25951 + (ri - 192);
        else               row = XGF + (ri - 737)*PW + 160;
        *(uint4*)(g_x + base + (size_t)row*128u + (uint32_t)c*16u) = z;
    }
    if (gy == 0)
        for (int i = threadIdx.x; i < C_; i += blockDim.x)
            g_pooled[b*C_ + i] = 0.f;
}

// transpose x -> g_x (fp16) + fused global-average-pool partial sums
__global__ __launch_bounds__(256)
void xprep_kernel(const float* __restrict__ x) {
    __shared__ float s[64*33];
    int h  = blockIdx.x;
    int w0 = blockIdx.y * 32;
    int b  = blockIdx.z;
    int t  = threadIdx.x;
    int wd = t >> 5, lane = t & 31;
    #pragma unroll
    for (int i = 0; i < 8; i++) {
        int c = i*8 + wd;
        s[c*33 + lane] = x[(((size_t)b*C_ + c)*H_ + h)*W_ + w0 + lane];
    }
    __syncthreads();
    int px = t >> 3, g = t & 7;
    unsigned short hs[8];
    #pragma unroll
    for (int j = 0; j < 8; j++) {
        float v = s[(8*g + j)*33 + px];
        hs[j] = __half_as_ushort(__float2half_rn(v));
    }
    uint4 hv;
    hv.x = hs[0] | ((uint32_t)hs[1] << 16); hv.y = hs[2] | ((uint32_t)hs[3] << 16);
    hv.z = hs[4] | ((uint32_t)hs[5] << 16); hv.w = hs[6] | ((uint32_t)hs[7] << 16);
    uint32_t row = XGF + (uint32_t)h*PW + (uint32_t)(w0 + px);
    *(uint4*)(g_x + (size_t)b*XREGB + (size_t)row*128u + (uint32_t)g*16u) = hv;

    if (t < 64) {
        float sum = 0.f;
        #pragma unroll
        for (int p = 0; p < 32; p++) sum += s[t*33 + p];
        atomicAdd(&g_pooled[b*C_ + t], sum);
    }
}

// fused attention + weight aggregation -> fp16. grid (B, 9 taps, 4 oc-groups), 128 thr.
__global__ __launch_bounds__(128)
void wprep_kernel(const float* __restrict__ fc1,
                  const float* __restrict__ fc2,
                  const float* __restrict__ bias_p,
                  const float* __restrict__ weight) {
    int b = blockIdx.x, tap = blockIdx.y, zg = blockIdx.z;
    int t = threadIdx.x, lane = t & 31;
    __shared__ float attn_s[KEXP];

    if (t < 32) {
        float hid = 0.f;
        if (lane < HID) {
            #pragma unroll
            for (int c = 0; c < C_; c++)
                hid += g_pooled[b*C_ + c] * (1.0f/(float)HW) * fc1[lane*C_ + c];
            hid = fmaxf(hid, 0.f);
        }
        // ALL 32 lanes execute every shfl (mask = full warp); only lanes<KEXP use it
        float lg = 0.f;
        #pragma unroll
        for (int j = 0; j < HID; j++) {
            float hj = __shfl_sync(0xffffffffu, hid, j);
            if (lane < KEXP) lg += hj * fc2[lane*HID + j];
        }
        lg *= (1.0f/TEMPR);
        float l0 = __shfl_sync(0xffffffffu, lg, 0);
        float l1 = __shfl_sync(0xffffffffu, lg, 1);
        float l2 = __shfl_sync(0xffffffffu, lg, 2);
        float l3 = __shfl_sync(0xffffffffu, lg, 3);
        if (lane == 0) {
            float m = fmaxf(fmaxf(l0,l1), fmaxf(l2,l3));
            float e0 = expf(l0-m), e1 = expf(l1-m), e2 = expf(l2-m), e3 = expf(l3-m);
            float inv = 1.f/(e0+e1+e2+e3);
            attn_s[0] = e0*inv; attn_s[1] = e1*inv; attn_s[2] = e2*inv; attn_s[3] = e3*inv;
        }
    }
    __syncthreads();
    float a0 = attn_s[0], a1 = attn_s[1], a2 = attn_s[2], a3 = attn_s[3];

    // bias aggregation (once per batch: tap 0, group 0)
    if (tap == 0 && zg == 0 && t < OUT_) {
        g_aggb[b*OUT_ + t] = a0*bias_p[t] + a1*bias_p[OUT_ + t]
                           + a2*bias_p[2*OUT_ + t] + a3*bias_p[3*OUT_ + t];
    }

    int oc = zg*16 + (t >> 3);      // 16 ocs per block
    int g  = t & 7;
    unsigned short hs[8];
    #pragma unroll
    for (int j = 0; j < 8; j++) {
        int c = 8*g + j;
        size_t e = ((size_t)oc*C_ + c)*9 + tap;
        size_t stride = (size_t)OUT_*C_*9;
        float s = a0*weight[e] + a1*weight[e + stride]
                + a2*weight[e + 2*stride] + a3*weight[e + 3*stride];
        hs[j] = __half_as_ushort(__float2half_rn(s));
    }
    uint4 hv;
    hv.x = hs[0] | ((uint32_t)hs[1] << 16); hv.y = hs[2] | ((uint32_t)hs[3] << 16);
    hv.z = hs[4] | ((uint32_t)hs[5] << 16); hv.w = hs[6] | ((uint32_t)hs[7] << 16);
    size_t tb = ((size_t)b*9 + tap)*8192;
    *(uint4*)(g_wp + tb + (size_t)oc*128u + g*16u) = hv;
}

// ================= conv: single-pass fp16 implicit GEMM =================
// CTA: 512 px x 64 oc, 16 warps (8m x 2n), warp tile 64 px x 32 oc.
__global__ __launch_bounds__(512, 1)
void conv_mma_kernel(float* __restrict__ out) {
    extern __shared__ unsigned char smem[];
    uint32_t sb = smem_u32(smem);
    int tid = threadIdx.x, wid = tid >> 5, lane = tid & 31;
    int b = blockIdx.y;
    int n0 = blockIdx.x * MTILE;

    // ---- stage x strip + ALL 9 weight taps ----
    {
        const unsigned char* xs = g_x + (size_t)b*XREGB + (size_t)(XGF + n0 - 162)*128;
        for (int i = tid; i < STRIP*8; i += 512) {
            int r = i >> 3, c = i & 7;
            cp16(sb + OFF_X + r*SROW_B + c*16, xs + (size_t)r*128 + c*16);
        }
        const unsigned char* ws = g_wp + (size_t)b*9*8192;
        for (int i = tid; i < 9*64*8; i += 512) {
            int tap = i / (64*8);
            int r   = (i >> 3) & 63;
            int c   = i & 7;
            cp16(sb + OFF_W + tap*WBUF_SZ + r*SROW_B + c*16,
                 ws + (size_t)tap*8192 + (size_t)r*128 + c*16);
        }
        CP_COMMIT();
        CP_WAIT0();
        __syncthreads();
    }

    const int wm = (wid & 7) * 64;          // 64 px per warp (4 m16 tiles)
    const int wn = (wid >> 3) * 32;         // 32 oc per warp (4 n8 tiles)
    const int shifts[9] = {-162,-161,-160,-1,0,1,160,161,162};

    float acc[4][4][4];
    #pragma unroll
    for (int i = 0; i < 4; i++)
        #pragma unroll
        for (int j = 0; j < 4; j++)
            #pragma unroll
            for (int k = 0; k < 4; k++) acc[i][j][k] = 0.f;

    const uint32_t a_lane = (uint32_t)(lane & 15)*SROW_B + (uint32_t)(lane >> 4)*16;
    const uint32_t b_lane = (uint32_t)((lane & 7) + ((lane >> 4) & 1)*8)*SROW_B
                          + (uint32_t)((lane >> 3) & 1)*16;

    #pragma unroll
    for (int tap = 0; tap < 9; tap++) {
        uint32_t wbuf = sb + OFF_W + (uint32_t)tap*WBUF_SZ;
        uint32_t xrow = sb + OFF_X + (uint32_t)(162 + shifts[tap] + wm)*SROW_B + a_lane;

        #pragma unroll
        for (int ks = 0; ks < 4; ks++) {
            uint32_t kb = (uint32_t)ks*32;               // 16 ch = 32 B
            uint32_t bf[2][4];
            #pragma unroll
            for (int nh = 0; nh < 2; nh++) {
                uint32_t ba = wbuf + (uint32_t)(wn + nh*16)*SROW_B + b_lane + kb;
                LDM4(bf[nh], ba);
            }
            #pragma unroll
            for (int mi = 0; mi < 4; mi++) {
                uint32_t af[4];
                LDM4(af, xrow + (uint32_t)mi*(16*SROW_B) + kb);
                #pragma unroll
                for (int nh = 0; nh < 2; nh++) {
                    MMA16816(acc[mi][nh*2 + 0], af, (bf[nh] + 0));
                    MMA16816(acc[mi][nh*2 + 1], af, (bf[nh] + 2));
                }
            }
        }
    }

    // ---- epilogue: direct stores with flat->(h,w) filtering ----
    int g = lane >> 2, tc = lane & 3;
    #pragma unroll
    for (int mi = 0; mi < 4; mi++) {
        #pragma unroll
        for (int ni = 0; ni < 4; ni++) {
            int oc = wn + ni*8 + tc*2;
            float2 bias = *(const float2*)&g_aggb[b*OUT_ + oc];
            int pxA = n0 + wm + mi*16 + g;
            #pragma unroll
            for (int half = 0; half < 2; half++) {
                int px = pxA + half*8;
                int h = px / PW;
                int w = px - h*PW;
                if (w < W_ && h < H_) {
                    size_t o = (((size_t)b*OUT_ + oc)*H_ + h)*W_ + w;
                    out[o]      = acc[mi][ni][half*2 + 0] + bias.x;
                    out[o + HW] = acc[mi][ni][half*2 + 1] + bias.y;
                }
            }
        }
    }
}

extern "C" void kernel_launch(void* const* d_in, const int* in_sizes, int n_in,
                              void* d_out, int out_size) {
    const float* x      = (const float*)d_in[0];
    const float* fc1    = (const float*)d_in[1];
    const float* fc2    = (const float*)d_in[2];
    const float* weight = (const float*)d_in[3];
    const float* bias_p = (const float*)d_in[4];
    float* out = (float*)d_out;

    cudaFuncSetAttribute(conv_mma_kernel, cudaFuncAttributeMaxDynamicSharedMemorySize, DYN_SMEM);

    border_zero_kernel<<<dim3(B_, 8), 128>>>();
    xprep_kernel<<<dim3(H_, 5, B_), 256>>>(x);
    wprep_kernel<<<dim3(B_, 9, 4), 128>>>(fc1, fc2, bias_p, weight);
    conv_mma_kernel<<<dim3(NT_PER_B, B_), 512, DYN_SMEM>>>(out);
}

// round 15
// speedup vs baseline: 6.9749x; 1.2021x over previous
#include <cuda_runtime.h>
#include <cuda_fp16.h>
#include <stdint.h>
#include <math.h>

#define B_    16
#define C_    64
#define H_    160
#define W_    160
#define OUT_  64
#define KEXP  4
#define HID   17
#define TEMPR 34.0f
#define HW    25600

// ---- flat padded image: [b][flat_px][64ch] fp16, 128B per pixel ----
// flat n = h*161 + w ; junction cell (w==160) + guards are never written and
// rely on CUDA's zero-initialization of __device__ globals (persistent).
#define PW      161
#define XGF     192                      // front guard rows
#define NPOS    25759                    // 159*161+159+1 output positions
#define XROWS   26496
#define XREGB   3391488ULL               // 26496*128
// ---- tiling ----
#define MTILE   256
#define NT_PER_B 101                     // ceil(25759/256)
#define STRIP   580                      // 256 + 2*162
#define SROW_B  144                      // padded smem row stride (bytes)
// ---- smem layout: x strip + double-buffered weights ----
#define OFF_X   0                        // 580*144 = 83520
#define OFF_W   83520
#define WBUF_SZ 9216                     // 64 rows * 144
#define DYN_SMEM 101952                  // 83520 + 2*9216  (2 CTAs/SM)

__device__ __align__(128) unsigned char g_x[16*XREGB];
__device__ __align__(128) unsigned char g_wp[16*9*8192];    // [b][tap][64 oc rows][128B]
__device__ float g_pooled[B_*C_];
__device__ float g_aggb[B_*OUT_];

__device__ __forceinline__ uint32_t smem_u32(const void* p) {
    uint32_t a;
    asm("{ .reg .u64 t; cvta.to.shared.u64 t, %1; cvt.u32.u64 %0, t; }" : "=r"(a) : "l"(p));
    return a;
}
__device__ __forceinline__ void cp16(uint32_t dst, const void* src) {
    asm volatile("cp.async.cg.shared.global [%0], [%1], 16;" :: "r"(dst), "l"(src) : "memory");
}
#define CP_COMMIT() asm volatile("cp.async.commit_group;" ::: "memory")
#define CP_WAIT0()  asm volatile("cp.async.wait_group 0;" ::: "memory")

#define LDM4(r, a) \
    asm volatile("ldmatrix.sync.aligned.m8n8.x4.shared.b16 {%0,%1,%2,%3}, [%4];" \
        : "=r"((r)[0]), "=r"((r)[1]), "=r"((r)[2]), "=r"((r)[3]) : "r"(a))
#define MMA16816(d, a, b) \
    asm volatile("mma.sync.aligned.m16n8k16.row.col.f32.f16.f16.f32 " \
        "{%0,%1,%2,%3}, {%4,%5,%6,%7}, {%8,%9}, {%0,%1,%2,%3};" \
        : "+f"((d)[0]), "+f"((d)[1]), "+f"((d)[2]), "+f"((d)[3]) \
        : "r"((a)[0]), "r"((a)[1]), "r"((a)[2]), "r"((a)[3]), "r"((b)[0]), "r"((b)[1]))

// ================= preprocessing =================
// zero ONLY the pooled accumulators (g_x guards are zero-init persistent)
__global__ void pool_zero_kernel() {
    g_pooled[threadIdx.x] = 0.f;
}

// transpose x -> g_x (fp16) + fused global-average-pool partial sums
__global__ __launch_bounds__(256)
void xprep_kernel(const float* __restrict__ x) {
    __shared__ float s[64*33];
    int h  = blockIdx.x;
    int w0 = blockIdx.y * 32;
    int b  = blockIdx.z;
    int t  = threadIdx.x;
    int wd = t >> 5, lane = t & 31;
    #pragma unroll
    for (int i = 0; i < 8; i++) {
        int c = i*8 + wd;
        s[c*33 + lane] = x[(((size_t)b*C_ + c)*H_ + h)*W_ + w0 + lane];
    }
    __syncthreads();
    int px = t >> 3, g = t & 7;
    unsigned short hs[8];
    #pragma unroll
    for (int j = 0; j < 8; j++) {
        float v = s[(8*g + j)*33 + px];
        hs[j] = __half_as_ushort(__float2half_rn(v));
    }
    uint4 hv;
    hv.x = hs[0] | ((uint32_t)hs[1] << 16); hv.y = hs[2] | ((uint32_t)hs[3] << 16);
    hv.z = hs[4] | ((uint32_t)hs[5] << 16); hv.w = hs[6] | ((uint32_t)hs[7] << 16);
    uint32_t row = XGF + (uint32_t)h*PW + (uint32_t)(w0 + px);
    *(uint4*)(g_x + (size_t)b*XREGB + (size_t)row*128u + (uint32_t)g*16u) = hv;

    if (t < 64) {
        float sum = 0.f;
        #pragma unroll
        for (int p = 0; p < 32; p++) sum += s[t*33 + p];
        atomicAdd(&g_pooled[b*C_ + t], sum);
    }
}

// fused attention + weight aggregation -> fp16. grid (B, 9 taps, 4 oc-groups), 128 thr.
__global__ __launch_bounds__(128)
void wprep_kernel(const float* __restrict__ fc1,
                  const float* __restrict__ fc2,
                  const float* __restrict__ bias_p,
                  const float* __restrict__ weight) {
    int b = blockIdx.x, tap = blockIdx.y, zg = blockIdx.z;
    int t = threadIdx.x, lane = t & 31;
    __shared__ float attn_s[KEXP];

    if (t < 32) {
        float hid = 0.f;
        if (lane < HID) {
            #pragma unroll
            for (int c = 0; c < C_; c++)
                hid += g_pooled[b*C_ + c] * (1.0f/(float)HW) * fc1[lane*C_ + c];
            hid = fmaxf(hid, 0.f);
        }
        float lg = 0.f;
        #pragma unroll
        for (int j = 0; j < HID; j++) {
            float hj = __shfl_sync(0xffffffffu, hid, j);
            if (lane < KEXP) lg += hj * fc2[lane*HID + j];
        }
        lg *= (1.0f/TEMPR);
        float l0 = __shfl_sync(0xffffffffu, lg, 0);
        float l1 = __shfl_sync(0xffffffffu, lg, 1);
        float l2 = __shfl_sync(0xffffffffu, lg, 2);
        float l3 = __shfl_sync(0xffffffffu, lg, 3);
        if (lane == 0) {
            float m = fmaxf(fmaxf(l0,l1), fmaxf(l2,l3));
            float e0 = expf(l0-m), e1 = expf(l1-m), e2 = expf(l2-m), e3 = expf(l3-m);
            float inv = 1.f/(e0+e1+e2+e3);
            attn_s[0] = e0*inv; attn_s[1] = e1*inv; attn_s[2] = e2*inv; attn_s[3] = e3*inv;
        }
    }
    __syncthreads();
    float a0 = attn_s[0], a1 = attn_s[1], a2 = attn_s[2], a3 = attn_s[3];

    if (tap == 0 && zg == 0 && t < OUT_) {
        g_aggb[b*OUT_ + t] = a0*bias_p[t] + a1*bias_p[OUT_ + t]
                           + a2*bias_p[2*OUT_ + t] + a3*bias_p[3*OUT_ + t];
    }

    int oc = zg*16 + (t >> 3);
    int g  = t & 7;
    unsigned short hs[8];
    #pragma unroll
    for (int j = 0; j < 8; j++) {
        int c = 8*g + j;
        size_t e = ((size_t)oc*C_ + c)*9 + tap;
        size_t stride = (size_t)OUT_*C_*9;
        float s = a0*weight[e] + a1*weight[e + stride]
                + a2*weight[e + 2*stride] + a3*weight[e + 3*stride];
        hs[j] = __half_as_ushort(__float2half_rn(s));
    }
    uint4 hv;
    hv.x = hs[0] | ((uint32_t)hs[1] << 16); hv.y = hs[2] | ((uint32_t)hs[3] << 16);
    hv.z = hs[4] | ((uint32_t)hs[5] << 16); hv.w = hs[6] | ((uint32_t)hs[7] << 16);
    size_t tb = ((size_t)b*9 + tap)*8192;
    *(uint4*)(g_wp + tb + (size_t)oc*128u + g*16u) = hv;
}

// ================= conv: single-pass fp16 implicit GEMM, 2 CTAs/SM =================
// CTA: 256 px x 64 oc, 8 warps (4m x 2n), warp tile 64 px x 32 oc.
// Weights double-buffered per tap (cp.async overlap with MMA).
__global__ __launch_bounds__(256, 2)
void conv_mma_kernel(float* __restrict__ out) {
    extern __shared__ unsigned char smem[];
    uint32_t sb = smem_u32(smem);
    int tid = threadIdx.x, wid = tid >> 5, lane = tid & 31;
    int b = blockIdx.y;
    int n0 = blockIdx.x * MTILE;

    // ---- stage x strip + W tap0 ----
    {
        const unsigned char* xs = g_x + (size_t)b*XREGB + (size_t)(XGF + n0 - 162)*128;
        for (int i = tid; i < STRIP*8; i += 256) {
            int r = i >> 3, c = i & 7;
            cp16(sb + OFF_X + r*SROW_B + c*16, xs + (size_t)r*128 + c*16);
        }
        const unsigned char* ws = g_wp + (size_t)b*9*8192;
        for (int i = tid; i < 64*8; i += 256) {
            int r = i >> 3, c = i & 7;
            cp16(sb + OFF_W + r*SROW_B + c*16, ws + (size_t)r*128 + c*16);
        }
        CP_COMMIT();
        CP_WAIT0();
        __syncthreads();
    }

    const int wm = (wid & 3) * 64;          // 64 px per warp (4 m16 tiles)
    const int wn = (wid >> 2) * 32;         // 32 oc per warp (4 n8 tiles)
    const int shifts[9] = {-162,-161,-160,-1,0,1,160,161,162};

    float acc[4][4][4];
    #pragma unroll
    for (int i = 0; i < 4; i++)
        #pragma unroll
        for (int j = 0; j < 4; j++)
            #pragma unroll
            for (int k = 0; k < 4; k++) acc[i][j][k] = 0.f;

    const uint32_t a_lane = (uint32_t)(lane & 15)*SROW_B + (uint32_t)(lane >> 4)*16;
    const uint32_t b_lane = (uint32_t)((lane & 7) + ((lane >> 4) & 1)*8)*SROW_B
                          + (uint32_t)((lane >> 3) & 1)*16;

    #pragma unroll
    for (int tap = 0; tap < 9; tap++) {
        // prefetch next tap's weights into the other buffer
        if (tap < 8) {
            const unsigned char* ws = g_wp + ((size_t)b*9 + tap + 1)*8192;
            uint32_t wdst = sb + OFF_W + ((tap + 1) & 1)*WBUF_SZ;
            for (int i = tid; i < 64*8; i += 256) {
                int r = i >> 3, c = i & 7;
                cp16(wdst + r*SROW_B + c*16, ws + (size_t)r*128 + c*16);
            }
            CP_COMMIT();
        }

        uint32_t wbuf = sb + OFF_W + (tap & 1)*WBUF_SZ;
        uint32_t xrow = sb + OFF_X + (uint32_t)(162 + shifts[tap] + wm)*SROW_B + a_lane;

        #pragma unroll
        for (int ks = 0; ks < 4; ks++) {
            uint32_t kb = (uint32_t)ks*32;               // 16 ch = 32 B
            uint32_t bf[2][4];
            #pragma unroll
            for (int nh = 0; nh < 2; nh++) {
                uint32_t ba = wbuf + (uint32_t)(wn + nh*16)*SROW_B + b_lane + kb;
                LDM4(bf[nh], ba);
            }
            #pragma unroll
            for (int mi = 0; mi < 4; mi++) {
                uint32_t af[4];
                LDM4(af, xrow + (uint32_t)mi*(16*SROW_B) + kb);
                #pragma unroll
                for (int nh = 0; nh < 2; nh++) {
                    MMA16816(acc[mi][nh*2 + 0], af, (bf[nh] + 0));
                    MMA16816(acc[mi][nh*2 + 1], af, (bf[nh] + 2));
                }
            }
        }
        if (tap < 8) { CP_WAIT0(); }
        __syncthreads();
    }

    // ---- epilogue: direct stores with flat->(h,w) filtering ----
    int g = lane >> 2, tc = lane & 3;
    #pragma unroll
    for (int mi = 0; mi < 4; mi++) {
        #pragma unroll
        for (int ni = 0; ni < 4; ni++) {
            int oc = wn + ni*8 + tc*2;
            float2 bias = *(const float2*)&g_aggb[b*OUT_ + oc];
            int pxA = n0 + wm + mi*16 + g;
            #pragma unroll
            for (int half = 0; half < 2; half++) {
                int px = pxA + half*8;
                int h = px / PW;
                int w = px - h*PW;
                if (w < W_ && h < H_) {
                    size_t o = (((size_t)b*OUT_ + oc)*H_ + h)*W_ + w;
                    out[o]      = acc[mi][ni][half*2 + 0] + bias.x;
                    out[o + HW] = acc[mi][ni][half*2 + 1] + bias.y;
                }
            }
        }
    }
}

extern "C" void kernel_launch(void* const* d_in, const int* in_sizes, int n_in,
                              void* d_out, int out_size) {
    const float* x      = (const float*)d_in[0];
    const float* fc1    = (const float*)d_in[1];
    const float* fc2    = (const float*)d_in[2];
    const float* weight = (const float*)d_in[3];
    const float* bias_p = (const float*)d_in[4];
    float* out = (float*)d_out;

    cudaFuncSetAttribute(conv_mma_kernel, cudaFuncAttributeMaxDynamicSharedMemorySize, DYN_SMEM);

    pool_zero_kernel<<<1, B_*C_>>>();
    xprep_kernel<<<dim3(H_, 5, B_), 256>>>(x);
    wprep_kernel<<<dim3(B_, 9, 4), 128>>>(fc1, fc2, bias_p, weight);
    conv_mma_kernel<<<dim3(NT_PER_B, B_), 256, DYN_SMEM>>>(out);
}